// round 6
// baseline (speedup 1.0000x reference)
#include <cuda_runtime.h>
#include <math.h>

#define N_NODES 200000
#define N_USERS 100000
#define DIM 64
#define E_MAX   1200000
#define NODES_PER_SCAN_BLK 1024
#define NUM_SCAN_BLOCKS ((N_NODES + NODES_PER_SCAN_BLK - 1) / NODES_PER_SCAN_BLK)  // 196

// ---- device scratch (static globals; no runtime allocation) ----
__device__ int   g_is64;
__device__ int   g_cnt[N_NODES];
__device__ int   g_off[N_NODES];
__device__ int   g_cur[N_NODES];
__device__ float g_dinv[N_NODES];
__device__ float g_a[N_NODES];          // a = A_norm . 1
__device__ int   g_chain[NUM_SCAN_BLOCKS];
__device__ int   g_src[E_MAX];
__device__ float g_Wc[64 * 64];         // W1 @ W2
__device__ float g_bv[64];              // b1 @ W2
__device__ float g_z[(size_t)N_NODES * DIM];   // y1 = A_norm x
__device__ float g_h[(size_t)N_NODES * DIM];   // y2 = A_norm y1

// robust index fetch: edge_index may be int64 or int32 depending on JAX x64 config
__device__ __forceinline__ int load_idx(const void* ei, size_t pos) {
    if (g_is64) return (int)((const long long*)ei)[pos];
    return ((const int*)ei)[pos];
}

// ------------------------------------------------------------------
// zero counters / chain flags + (block 0) detect edge dtype
__global__ void k_zero(const unsigned int* __restrict__ raw) {
    int i = blockIdx.x * blockDim.x + threadIdx.x;
    if (i < N_NODES) g_cnt[i] = 0;
    if (i < NUM_SCAN_BLOCKS) g_chain[i] = 0;
    if (blockIdx.x == 0) {
        __shared__ int any_hi;
        if (threadIdx.x == 0) any_hi = 0;
        __syncthreads();
        if (raw[threadIdx.x * 2 + 1] != 0u) any_hi = 1;  // benign race
        __syncthreads();
        if (threadIdx.x == 0) g_is64 = (any_hi == 0);
    }
}

// in-degree histogram over col = edge_index[1]
__global__ void k_hist(const void* __restrict__ ei, int E) {
    int e = blockIdx.x * blockDim.x + threadIdx.x;
    if (e < E) {
        int c = load_idx(ei, (size_t)E + e);
        if ((unsigned)c < (unsigned)N_NODES) atomicAdd(&g_cnt[c], 1);
    }
}

// ---- single-pass chained scan: offsets + cursors + dinv in ONE kernel ----
// 196 blocks x 256 thr, tiny smem: all co-resident -> forward-progress safe.
__global__ __launch_bounds__(256) void k_scanF() {
    __shared__ int sbuf[2][256];
    __shared__ int s_base;
    int t = threadIdx.x, b = blockIdx.x;
    int base = b * NODES_PER_SCAN_BLK + t * 4;
    int v[4]; int sum = 0;
#pragma unroll
    for (int q = 0; q < 4; ++q) {
        v[q] = (base + q < N_NODES) ? g_cnt[base + q] : 0;
        sum += v[q];
    }
    sbuf[0][t] = sum;
    __syncthreads();
    int cur = 0;
#pragma unroll
    for (int d = 1; d < 256; d <<= 1) {
        int x = sbuf[cur][t];
        if (t >= d) x += sbuf[cur][t - d];
        sbuf[1 - cur][t] = x;
        cur ^= 1;
        __syncthreads();
    }
    int incl = sbuf[cur][t];
    int block_total = sbuf[cur][255];
    if (t == 0) {
        int c = 0;
        if (b > 0) {
            while ((c = atomicAdd(&g_chain[b - 1], 0)) == 0) { }
            c -= 1;                              // published as prefix+1
        }
        atomicExch(&g_chain[b], c + block_total + 1);
        s_base = c;
    }
    __syncthreads();
    int excl = s_base + incl - sum;
#pragma unroll
    for (int q = 0; q < 4; ++q) {
        int idx = base + q;
        if (idx < N_NODES) {
            g_off[idx] = excl;
            g_cur[idx] = excl;
            g_dinv[idx] = rsqrtf((float)(v[q] + 1));   // +1 self-loop
        }
        excl += v[q];
    }
}

// scatter edge sources into dest-keyed CSR buckets
__global__ void k_fill(const void* __restrict__ ei, int E) {
    int e = blockIdx.x * blockDim.x + threadIdx.x;
    if (e < E) {
        int c = load_idx(ei, (size_t)E + e);
        int s = load_idx(ei, (size_t)e);
        if ((unsigned)c < (unsigned)N_NODES && (unsigned)s < (unsigned)N_NODES) {
            int p = atomicAdd(&g_cur[c], 1);
            g_src[p] = s;
        }
    }
}

// ------------------------------------------------------------------
// one block: Wc = W1 @ W2 (64x64x64) and bv = b1 @ W2
__global__ __launch_bounds__(256) void k_wc(
    const float* __restrict__ W1, const float* __restrict__ W2,
    const float* __restrict__ b1)
{
    __shared__ float w1s[64 * 64];
    __shared__ float w2s[64 * 64];
    int t = threadIdx.x;
    for (int i = t; i < 1024; i += 256) {
        ((float4*)w1s)[i] = ((const float4*)W1)[i];
        ((float4*)w2s)[i] = ((const float4*)W2)[i];
    }
    __syncthreads();
    int row = t >> 2;
    int cb  = (t & 3) * 16;
    float acc[16];
#pragma unroll
    for (int j = 0; j < 16; ++j) acc[j] = 0.f;
    for (int k = 0; k < 64; ++k) {
        float a = w1s[row * 64 + k];
#pragma unroll
        for (int j = 0; j < 16; ++j)
            acc[j] = fmaf(a, w2s[k * 64 + cb + j], acc[j]);
    }
#pragma unroll
    for (int j = 0; j < 16; ++j) g_Wc[row * 64 + cb + j] = acc[j];
    if (t < 64) {
        float s = 0.f;
        for (int k = 0; k < 64; ++k) s = fmaf(b1[k], w2s[k * 64 + t], s);
        g_bv[t] = s;
    }
}

// ------------------------------------------------------------------
// y[c,:] = dinv[c] * (dinv[c]*x[c,:] + sum_{e->c} dinv[src]*x[src,:])
// mode 0: src = concat(user,item) -> dst g_z, also a[c]
// mode 1: src = g_z              -> dst g_h
// (device-scratch buffers selected INSIDE the kernel; never host-passed)
__global__ __launch_bounds__(256) void k_agg(
    const float* __restrict__ xa, const float* __restrict__ xb, int mode)
{
    int t = blockIdx.x * blockDim.x + threadIdx.x;
    int node = t >> 4;
    if (node >= N_NODES) return;
    int lane = (t & 15) * 4;

    float dn = g_dinv[node];

    const float* xrow;
    if (mode == 0)
        xrow = (node < N_USERS) ? (xa + (size_t)node * DIM)
                                : (xb + (size_t)(node - N_USERS) * DIM);
    else
        xrow = g_z + (size_t)node * DIM;

    float4 self = *(const float4*)(xrow + lane);
    float4 acc0 = make_float4(dn * self.x, dn * self.y, dn * self.z, dn * self.w);
    float4 acc1 = make_float4(0.f, 0.f, 0.f, 0.f);
    float asum0 = dn, asum1 = 0.f;

    int s0 = g_off[node];
    int cnt = g_cur[node] - s0;
    int i = 0;
    for (; i + 2 <= cnt; i += 2) {
        int srcA = g_src[s0 + i];
        int srcB = g_src[s0 + i + 1];
        float dA = g_dinv[srcA];
        float dB = g_dinv[srcB];
        const float* ra;
        const float* rb;
        if (mode == 0) {
            ra = (srcA < N_USERS) ? (xa + (size_t)srcA * DIM)
                                  : (xb + (size_t)(srcA - N_USERS) * DIM);
            rb = (srcB < N_USERS) ? (xa + (size_t)srcB * DIM)
                                  : (xb + (size_t)(srcB - N_USERS) * DIM);
        } else {
            ra = g_z + (size_t)srcA * DIM;
            rb = g_z + (size_t)srcB * DIM;
        }
        float4 va = *(const float4*)(ra + lane);
        float4 vb = *(const float4*)(rb + lane);
        acc0.x = fmaf(dA, va.x, acc0.x); acc0.y = fmaf(dA, va.y, acc0.y);
        acc0.z = fmaf(dA, va.z, acc0.z); acc0.w = fmaf(dA, va.w, acc0.w);
        acc1.x = fmaf(dB, vb.x, acc1.x); acc1.y = fmaf(dB, vb.y, acc1.y);
        acc1.z = fmaf(dB, vb.z, acc1.z); acc1.w = fmaf(dB, vb.w, acc1.w);
        asum0 += dA; asum1 += dB;
    }
    if (i < cnt) {
        int srcA = g_src[s0 + i];
        float dA = g_dinv[srcA];
        const float* ra;
        if (mode == 0)
            ra = (srcA < N_USERS) ? (xa + (size_t)srcA * DIM)
                                  : (xb + (size_t)(srcA - N_USERS) * DIM);
        else
            ra = g_z + (size_t)srcA * DIM;
        float4 va = *(const float4*)(ra + lane);
        acc0.x = fmaf(dA, va.x, acc0.x); acc0.y = fmaf(dA, va.y, acc0.y);
        acc0.z = fmaf(dA, va.z, acc0.z); acc0.w = fmaf(dA, va.w, acc0.w);
        asum0 += dA;
    }
    float4 o = make_float4(dn * (acc0.x + acc1.x), dn * (acc0.y + acc1.y),
                           dn * (acc0.z + acc1.z), dn * (acc0.w + acc1.w));
    float* dst = (mode == 0) ? g_z : g_h;
    *(float4*)(dst + (size_t)node * DIM + lane) = o;
    if (mode == 0 && (t & 15) == 0) g_a[node] = dn * (asum0 + asum1);
}

// ------------------------------------------------------------------
// out[r,:] = g_h[r,:] @ Wc + a[r]*bv + b2   (64 rows/block, 4x4 micro-tile)
__global__ __launch_bounds__(256) void k_gemm(
    const float* __restrict__ b2, float* __restrict__ out)
{
    __shared__ __align__(16) float Ws[64 * 64];
    __shared__ __align__(16) float xs[64][68];
    __shared__ float bvs[64], b2s[64];
    int tid = threadIdx.x;
    int block_row = blockIdx.x * 64;

    for (int i = tid; i < 1024; i += 256)
        ((float4*)Ws)[i] = ((const float4*)g_Wc)[i];
    if (tid < 64) { bvs[tid] = g_bv[tid]; b2s[tid] = b2[tid]; }

    {
        int r = tid >> 2;
        int kb = (tid & 3) * 16;
        int gr = block_row + r;
        int cr = (gr < N_NODES) ? gr : (N_NODES - 1);
        const float* xrow = g_h + (size_t)cr * DIM;
#pragma unroll
        for (int q = 0; q < 4; ++q)
            *(float4*)(&xs[r][kb + q * 4]) = *(const float4*)(xrow + kb + q * 4);
    }
    __syncthreads();

    int ty = tid >> 4, tx = tid & 15;
    float acc[4][4] = {};
#pragma unroll 16
    for (int k = 0; k < 64; ++k) {
        float4 wv = *(const float4*)(Ws + k * 64 + tx * 4);
#pragma unroll
        for (int i = 0; i < 4; ++i) {
            float xv = xs[ty * 4 + i][k];
            acc[i][0] = fmaf(xv, wv.x, acc[i][0]);
            acc[i][1] = fmaf(xv, wv.y, acc[i][1]);
            acc[i][2] = fmaf(xv, wv.z, acc[i][2]);
            acc[i][3] = fmaf(xv, wv.w, acc[i][3]);
        }
    }
    float4 bvv = *(const float4*)(bvs + tx * 4);
    float4 b2v = *(const float4*)(b2s + tx * 4);
#pragma unroll
    for (int i = 0; i < 4; ++i) {
        int gr = block_row + ty * 4 + i;
        if (gr < N_NODES) {
            float av = g_a[gr];
            float4 o = make_float4(
                fmaf(av, bvv.x, acc[i][0]) + b2v.x,
                fmaf(av, bvv.y, acc[i][1]) + b2v.y,
                fmaf(av, bvv.z, acc[i][2]) + b2v.z,
                fmaf(av, bvv.w, acc[i][3]) + b2v.w);
            *(float4*)(out + (size_t)gr * DIM + tx * 4) = o;
        }
    }
}

// ------------------------------------------------------------------
extern "C" void kernel_launch(void* const* d_in, const int* in_sizes, int n_in,
                              void* d_out, int out_size)
{
    const void*  ei   = d_in[0];
    const float* user = (const float*)d_in[1];
    const float* item = (const float*)d_in[2];
    const float* W1   = (const float*)d_in[3];
    const float* b1   = (const float*)d_in[4];
    const float* W2   = (const float*)d_in[5];
    const float* b2   = (const float*)d_in[6];
    float* out        = (float*)d_out;
    int E = in_sizes[0] / 2;

    int zb = (N_NODES + 255) / 256;
    int eb = (E + 255) / 256;

    // graph prep (every launch; kernels only -> graph-capturable)
    k_zero<<<zb, 256>>>((const unsigned int*)ei);
    k_hist<<<eb, 256>>>(ei, E);
    k_scanF<<<NUM_SCAN_BLOCKS, 256>>>();
    k_fill<<<eb, 256>>>(ei, E);
    k_wc<<<1, 256>>>(W1, W2, b1);

    int agg_blocks  = (N_NODES * 16 + 255) / 256;   // 12500
    int gemm_blocks = (N_NODES + 63) / 64;          // 3125

    k_agg<<<agg_blocks, 256>>>(user, item, 0);   // y1 = A x  (-> g_z, + a)
    k_agg<<<agg_blocks, 256>>>(nullptr, nullptr, 1); // y2 = A y1 (-> g_h)
    k_gemm<<<gemm_blocks, 256>>>(b2, out);       // out = y2 Wc + a bv + b2
}

// round 7
// speedup vs baseline: 1.0596x; 1.0596x over previous
#include <cuda_runtime.h>
#include <math.h>

#define N_NODES 200000
#define N_USERS 100000
#define DIM 64
#define E_MAX   1200000
#define NODES_PER_SCAN_BLK 1024
#define NUM_SCAN_BLOCKS ((N_NODES + NODES_PER_SCAN_BLK - 1) / NODES_PER_SCAN_BLK)  // 196

// ---- device scratch (static globals; no runtime allocation) ----
__device__ int   g_is64;
__device__ int   g_cnt[N_NODES];
__device__ int   g_off[N_NODES];
__device__ int   g_cur[N_NODES];
__device__ float g_dinv[N_NODES];
__device__ float g_asum[N_NODES];       // sum of dinv[src] per dest (REDG in fill)
__device__ float g_a[N_NODES];          // a = A_norm . 1
__device__ int   g_chain[NUM_SCAN_BLOCKS];
__device__ int   g_src[E_MAX];
__device__ float g_Wc[64 * 64];         // W1 @ W2
__device__ float g_bv[64];              // b1 @ W2
__device__ float g_z[(size_t)N_NODES * DIM];   // zs = dinv * x
__device__ float g_h[(size_t)N_NODES * DIM];   // u1 = dinv^2 (zs + gather)

// robust index fetch: edge_index may be int64 or int32 depending on JAX x64 config
__device__ __forceinline__ int load_idx(const void* ei, size_t pos) {
    if (g_is64) return (int)((const long long*)ei)[pos];
    return ((const int*)ei)[pos];
}
// two consecutive indices (pos 16B-aligned for int64 path when pos is even)
__device__ __forceinline__ void load_idx2(const void* ei, size_t pos, int& a, int& b) {
    if (g_is64) {
        longlong2 v = *(const longlong2*)((const long long*)ei + pos);
        a = (int)v.x; b = (int)v.y;
    } else {
        int2 v = *(const int2*)((const int*)ei + pos);
        a = v.x; b = v.y;
    }
}

// ------------------------------------------------------------------
// zero counters / asum / chain flags + (block 0) detect edge dtype
__global__ void k_zero(const unsigned int* __restrict__ raw) {
    int i = blockIdx.x * blockDim.x + threadIdx.x;
    if (i < N_NODES) { g_cnt[i] = 0; g_asum[i] = 0.f; }
    if (i < NUM_SCAN_BLOCKS) g_chain[i] = 0;
    if (blockIdx.x == 0) {
        __shared__ int any_hi;
        if (threadIdx.x == 0) any_hi = 0;
        __syncthreads();
        if (raw[threadIdx.x * 2 + 1] != 0u) any_hi = 1;  // benign race
        __syncthreads();
        if (threadIdx.x == 0) g_is64 = (any_hi == 0);
    }
}

// in-degree histogram over col = edge_index[1]; 2 edges per thread
__global__ void k_hist(const void* __restrict__ ei, int E) {
    int e = (blockIdx.x * blockDim.x + threadIdx.x) * 2;
    if (e + 1 < E) {
        int c0, c1;
        load_idx2(ei, (size_t)E + e, c0, c1);
        if ((unsigned)c0 < (unsigned)N_NODES) atomicAdd(&g_cnt[c0], 1);
        if ((unsigned)c1 < (unsigned)N_NODES) atomicAdd(&g_cnt[c1], 1);
    } else if (e < E) {
        int c = load_idx(ei, (size_t)E + e);
        if ((unsigned)c < (unsigned)N_NODES) atomicAdd(&g_cnt[c], 1);
    }
}

// ---- single-pass chained scan: offsets + cursors + dinv in ONE kernel ----
__global__ __launch_bounds__(256) void k_scanF() {
    __shared__ int sbuf[2][256];
    __shared__ int s_base;
    int t = threadIdx.x, b = blockIdx.x;
    int base = b * NODES_PER_SCAN_BLK + t * 4;
    int v[4]; int sum = 0;
#pragma unroll
    for (int q = 0; q < 4; ++q) {
        v[q] = (base + q < N_NODES) ? g_cnt[base + q] : 0;
        sum += v[q];
    }
    sbuf[0][t] = sum;
    __syncthreads();
    int cur = 0;
#pragma unroll
    for (int d = 1; d < 256; d <<= 1) {
        int x = sbuf[cur][t];
        if (t >= d) x += sbuf[cur][t - d];
        sbuf[1 - cur][t] = x;
        cur ^= 1;
        __syncthreads();
    }
    int incl = sbuf[cur][t];
    int block_total = sbuf[cur][255];
    if (t == 0) {
        int c = 0;
        if (b > 0) {
            while ((c = atomicAdd(&g_chain[b - 1], 0)) == 0) { }
            c -= 1;                              // published as prefix+1
        }
        atomicExch(&g_chain[b], c + block_total + 1);
        s_base = c;
    }
    __syncthreads();
    int excl = s_base + incl - sum;
#pragma unroll
    for (int q = 0; q < 4; ++q) {
        int idx = base + q;
        if (idx < N_NODES) {
            g_off[idx] = excl;
            g_cur[idx] = excl;
            g_dinv[idx] = rsqrtf((float)(v[q] + 1));   // +1 self-loop
        }
        excl += v[q];
    }
}

// scatter srcs into dest-keyed CSR buckets + accumulate sum(dinv[src]) per dest
__global__ void k_fill(const void* __restrict__ ei, int E) {
    int e = (blockIdx.x * blockDim.x + threadIdx.x) * 2;
    if (e + 1 < E) {
        int c0, c1, s0, s1;
        load_idx2(ei, (size_t)E + e, c0, c1);
        load_idx2(ei, (size_t)e, s0, s1);
        if ((unsigned)c0 < (unsigned)N_NODES && (unsigned)s0 < (unsigned)N_NODES) {
            int p = atomicAdd(&g_cur[c0], 1);
            g_src[p] = s0;
            atomicAdd(&g_asum[c0], g_dinv[s0]);   // REDG, no return use
        }
        if ((unsigned)c1 < (unsigned)N_NODES && (unsigned)s1 < (unsigned)N_NODES) {
            int p = atomicAdd(&g_cur[c1], 1);
            g_src[p] = s1;
            atomicAdd(&g_asum[c1], g_dinv[s1]);
        }
    } else if (e < E) {
        int c = load_idx(ei, (size_t)E + e);
        int s = load_idx(ei, (size_t)e);
        if ((unsigned)c < (unsigned)N_NODES && (unsigned)s < (unsigned)N_NODES) {
            int p = atomicAdd(&g_cur[c], 1);
            g_src[p] = s;
            atomicAdd(&g_asum[c], g_dinv[s]);
        }
    }
}

// ------------------------------------------------------------------
// one block: Wc = W1 @ W2 (64x64x64) and bv = b1 @ W2
__global__ __launch_bounds__(256) void k_wc(
    const float* __restrict__ W1, const float* __restrict__ W2,
    const float* __restrict__ b1)
{
    __shared__ float w1s[64 * 64];
    __shared__ float w2s[64 * 64];
    int t = threadIdx.x;
    for (int i = t; i < 1024; i += 256) {
        ((float4*)w1s)[i] = ((const float4*)W1)[i];
        ((float4*)w2s)[i] = ((const float4*)W2)[i];
    }
    __syncthreads();
    int row = t >> 2;
    int cb  = (t & 3) * 16;
    float acc[16];
#pragma unroll
    for (int j = 0; j < 16; ++j) acc[j] = 0.f;
    for (int k = 0; k < 64; ++k) {
        float a = w1s[row * 64 + k];
#pragma unroll
        for (int j = 0; j < 16; ++j)
            acc[j] = fmaf(a, w2s[k * 64 + cb + j], acc[j]);
    }
#pragma unroll
    for (int j = 0; j < 16; ++j) g_Wc[row * 64 + cb + j] = acc[j];
    if (t < 64) {
        float s = 0.f;
        for (int k = 0; k < 64; ++k) s = fmaf(b1[k], w2s[k * 64 + t], s);
        g_bv[t] = s;
    }
}

// ------------------------------------------------------------------
// zs[i,:] = dinv[i] * x[i,:]  (resolve user/item split once; leaves zs L2-hot)
__global__ __launch_bounds__(256) void k_pre(
    const float* __restrict__ xa, const float* __restrict__ xb)
{
    int t = blockIdx.x * blockDim.x + threadIdx.x;
    int node = t >> 4;
    if (node >= N_NODES) return;
    int lane = (t & 15) * 4;
    const float* xrow = (node < N_USERS) ? (xa + (size_t)node * DIM)
                                         : (xb + (size_t)(node - N_USERS) * DIM);
    float dn = g_dinv[node];
    float4 v = *(const float4*)(xrow + lane);
    *(float4*)(g_z + (size_t)node * DIM + lane) =
        make_float4(dn * v.x, dn * v.y, dn * v.z, dn * v.w);
}

// ------------------------------------------------------------------
// u1[c,:] = dinv^2[c] * (zs[c,:] + sum_{e->c} zs[src,:])  — pure-add loop
// also finalize a[c] = dinv[c]*(dinv[c] + asum[c])
__global__ __launch_bounds__(256) void k_agg1()
{
    int t = blockIdx.x * blockDim.x + threadIdx.x;
    int node = t >> 4;
    if (node >= N_NODES) return;
    int lane = (t & 15) * 4;

    float4 acc = *(const float4*)(g_z + (size_t)node * DIM + lane);  // self
    int s0 = g_off[node];
    int cnt = g_cur[node] - s0;
    for (int i = 0; i < cnt; ++i) {
        int src = g_src[s0 + i];
        float4 v = *(const float4*)(g_z + (size_t)src * DIM + lane);
        acc.x += v.x; acc.y += v.y; acc.z += v.z; acc.w += v.w;
    }
    float dn = g_dinv[node];
    float d2 = dn * dn;
    *(float4*)(g_h + (size_t)node * DIM + lane) =
        make_float4(d2 * acc.x, d2 * acc.y, d2 * acc.z, d2 * acc.w);
    if ((t & 15) == 0) g_a[node] = dn * (dn + g_asum[node]);
}

// ------------------------------------------------------------------
// Fused agg2 + GEMM:
//   y2[r,:] = dinv[r] * (u1[r,:] + sum u1[src,:])   (gathered into smem tile)
//   out[r,:] = y2[r,:] @ Wc + a[r]*bv + b2
// 64 rows/block (3125 blocks exactly cover 200000), 256 threads.
__global__ __launch_bounds__(256) void k_gemm(
    const float* __restrict__ b2, float* __restrict__ out)
{
    __shared__ __align__(16) float Ws[64 * 64];
    __shared__ __align__(16) float xs[64][68];
    __shared__ float bvs[64], b2s[64];
    int tid = threadIdx.x;
    int block_row = blockIdx.x * 64;

    for (int i = tid; i < 1024; i += 256)
        ((float4*)Ws)[i] = ((const float4*)g_Wc)[i];
    if (tid < 64) { bvs[tid] = g_bv[tid]; b2s[tid] = b2[tid]; }

    // phase A: gather y2 rows into xs (16 lanes per node, 4 node-passes)
    {
        int lane = (tid & 15) * 4;
#pragma unroll
        for (int q = 0; q < 4; ++q) {
            int r = (tid >> 4) + q * 16;          // 0..63
            int node = block_row + r;
            float4 acc = *(const float4*)(g_h + (size_t)node * DIM + lane); // self
            int s0 = g_off[node];
            int cnt = g_cur[node] - s0;
            for (int i = 0; i < cnt; ++i) {
                int src = g_src[s0 + i];
                float4 v = *(const float4*)(g_h + (size_t)src * DIM + lane);
                acc.x += v.x; acc.y += v.y; acc.z += v.z; acc.w += v.w;
            }
            float dn = g_dinv[node];
            *(float4*)(&xs[r][lane]) =
                make_float4(dn * acc.x, dn * acc.y, dn * acc.z, dn * acc.w);
        }
    }
    __syncthreads();

    // phase B: 4x4 micro-tile FFMA GEMM
    int ty = tid >> 4, tx = tid & 15;
    float acc[4][4] = {};
#pragma unroll 16
    for (int k = 0; k < 64; ++k) {
        float4 wv = *(const float4*)(Ws + k * 64 + tx * 4);
#pragma unroll
        for (int i = 0; i < 4; ++i) {
            float xv = xs[ty * 4 + i][k];
            acc[i][0] = fmaf(xv, wv.x, acc[i][0]);
            acc[i][1] = fmaf(xv, wv.y, acc[i][1]);
            acc[i][2] = fmaf(xv, wv.z, acc[i][2]);
            acc[i][3] = fmaf(xv, wv.w, acc[i][3]);
        }
    }
    float4 bvv = *(const float4*)(bvs + tx * 4);
    float4 b2v = *(const float4*)(b2s + tx * 4);
#pragma unroll
    for (int i = 0; i < 4; ++i) {
        int gr = block_row + ty * 4 + i;
        float av = g_a[gr];
        float4 o = make_float4(
            fmaf(av, bvv.x, acc[i][0]) + b2v.x,
            fmaf(av, bvv.y, acc[i][1]) + b2v.y,
            fmaf(av, bvv.z, acc[i][2]) + b2v.z,
            fmaf(av, bvv.w, acc[i][3]) + b2v.w);
        *(float4*)(out + (size_t)gr * DIM + tx * 4) = o;
    }
}

// ------------------------------------------------------------------
extern "C" void kernel_launch(void* const* d_in, const int* in_sizes, int n_in,
                              void* d_out, int out_size)
{
    const void*  ei   = d_in[0];
    const float* user = (const float*)d_in[1];
    const float* item = (const float*)d_in[2];
    const float* W1   = (const float*)d_in[3];
    const float* b1   = (const float*)d_in[4];
    const float* W2   = (const float*)d_in[5];
    const float* b2   = (const float*)d_in[6];
    float* out        = (float*)d_out;
    int E = in_sizes[0] / 2;

    int zb  = (N_NODES + 255) / 256;
    int eb2 = (E / 2 + 255) / 256;

    // graph prep (every launch; kernels only -> graph-capturable)
    k_zero<<<zb, 256>>>((const unsigned int*)ei);
    k_hist<<<eb2, 256>>>(ei, E);
    k_scanF<<<NUM_SCAN_BLOCKS, 256>>>();
    k_fill<<<eb2, 256>>>(ei, E);
    k_wc<<<1, 256>>>(W1, W2, b1);

    int node_blocks = (N_NODES * 16 + 255) / 256;   // 12500
    int gemm_blocks = N_NODES / 64;                 // 3125 (exact)

    k_pre<<<node_blocks, 256>>>(user, item);   // zs = dinv*x      -> g_z
    k_agg1<<<node_blocks, 256>>>();            // u1, a            -> g_h, g_a
    k_gemm<<<gemm_blocks, 256>>>(b2, out);     // fused agg2+GEMM  -> out
}

// round 8
// speedup vs baseline: 1.4408x; 1.3597x over previous
#include <cuda_runtime.h>
#include <math.h>

#define N_NODES 200000
#define N_USERS 100000
#define DIM 64
#define E_MAX   1200000
#define NODES_PER_SCAN_BLK 1024
#define NUM_SCAN_BLOCKS ((N_NODES + NODES_PER_SCAN_BLK - 1) / NODES_PER_SCAN_BLK)  // 196

// ---- device scratch (static globals; no runtime allocation) ----
__device__ int   g_is64;
__device__ int   g_cnt[N_NODES];
__device__ int   g_off[N_NODES];
__device__ int   g_cur[N_NODES];
__device__ float g_dinv[N_NODES];
__device__ float g_asum[N_NODES];       // sum of dinv[src] per dest (REDG in fill)
__device__ float g_a[N_NODES];          // a = A_norm . 1
__device__ int   g_bsum[NUM_SCAN_BLOCKS];
__device__ int   g_bpre[NUM_SCAN_BLOCKS];
__device__ int   g_src[E_MAX];
__device__ float g_Wc[64 * 64];         // W1 @ W2
__device__ float g_bv[64];              // b1 @ W2
__device__ float g_z[(size_t)N_NODES * DIM];   // zs = dinv*x ; later y2
__device__ float g_h[(size_t)N_NODES * DIM];   // u1

// robust index fetch: edge_index may be int64 or int32 depending on JAX x64 config
__device__ __forceinline__ int load_idx(const void* ei, size_t pos) {
    if (g_is64) return (int)((const long long*)ei)[pos];
    return ((const int*)ei)[pos];
}
__device__ __forceinline__ void load_idx2(const void* ei, size_t pos, int& a, int& b) {
    if (g_is64) {
        longlong2 v = *(const longlong2*)((const long long*)ei + pos);
        a = (int)v.x; b = (int)v.y;
    } else {
        int2 v = *(const int2*)((const int*)ei + pos);
        a = v.x; b = v.y;
    }
}

// ------------------------------------------------------------------
// zero counters/asum + (block 0) detect edge dtype
__global__ void k_zero(const unsigned int* __restrict__ raw) {
    int i = blockIdx.x * blockDim.x + threadIdx.x;
    if (i < N_NODES) { g_cnt[i] = 0; g_asum[i] = 0.f; }
    if (blockIdx.x == 0) {
        __shared__ int any_hi;
        if (threadIdx.x == 0) any_hi = 0;
        __syncthreads();
        if (raw[threadIdx.x * 2 + 1] != 0u) any_hi = 1;  // benign race
        __syncthreads();
        if (threadIdx.x == 0) g_is64 = (any_hi == 0);
    }
}

// in-degree histogram over col = edge_index[1]; 2 edges per thread
__global__ void k_hist(const void* __restrict__ ei, int E) {
    int e = (blockIdx.x * blockDim.x + threadIdx.x) * 2;
    if (e + 1 < E) {
        int c0, c1;
        load_idx2(ei, (size_t)E + e, c0, c1);
        if ((unsigned)c0 < (unsigned)N_NODES) atomicAdd(&g_cnt[c0], 1);
        if ((unsigned)c1 < (unsigned)N_NODES) atomicAdd(&g_cnt[c1], 1);
    } else if (e < E) {
        int c = load_idx(ei, (size_t)E + e);
        if ((unsigned)c < (unsigned)N_NODES) atomicAdd(&g_cnt[c], 1);
    }
}

// ---- prefix scan: R2-proven 3-kernel version (parallel, ~16us total) ----
__global__ __launch_bounds__(256) void k_scan1() {
    __shared__ int sbuf[2][256];
    int t = threadIdx.x;
    int base = blockIdx.x * NODES_PER_SCAN_BLK + t * 4;
    int v[4]; int sum = 0;
#pragma unroll
    for (int q = 0; q < 4; ++q) {
        v[q] = (base + q < N_NODES) ? g_cnt[base + q] : 0;
        sum += v[q];
    }
    sbuf[0][t] = sum;
    __syncthreads();
    int cur = 0;
#pragma unroll
    for (int d = 1; d < 256; d <<= 1) {
        int x = sbuf[cur][t];
        if (t >= d) x += sbuf[cur][t - d];
        sbuf[1 - cur][t] = x;
        cur ^= 1;
        __syncthreads();
    }
    int incl = sbuf[cur][t];
    int excl = incl - sum;
#pragma unroll
    for (int q = 0; q < 4; ++q) {
        if (base + q < N_NODES) g_off[base + q] = excl;
        excl += v[q];
    }
    if (t == 255) g_bsum[blockIdx.x] = incl;
}

__global__ __launch_bounds__(256) void k_scan2() {
    __shared__ int sbuf[2][256];
    int t = threadIdx.x;
    int val = (t < NUM_SCAN_BLOCKS) ? g_bsum[t] : 0;
    sbuf[0][t] = val;
    __syncthreads();
    int cur = 0;
#pragma unroll
    for (int d = 1; d < 256; d <<= 1) {
        int x = sbuf[cur][t];
        if (t >= d) x += sbuf[cur][t - d];
        sbuf[1 - cur][t] = x;
        cur ^= 1;
        __syncthreads();
    }
    if (t < NUM_SCAN_BLOCKS) g_bpre[t] = sbuf[cur][t] - val;
}

__global__ void k_scan3() {
    int idx = blockIdx.x * blockDim.x + threadIdx.x;
    if (idx < N_NODES) {
        int off = g_off[idx] + g_bpre[idx / NODES_PER_SCAN_BLK];
        g_off[idx] = off;
        g_cur[idx] = off;
        g_dinv[idx] = rsqrtf((float)(g_cnt[idx] + 1));  // +1 self-loop
    }
}

// scatter srcs into dest-keyed CSR buckets + accumulate sum(dinv[src]) per dest
__global__ void k_fill(const void* __restrict__ ei, int E) {
    int e = (blockIdx.x * blockDim.x + threadIdx.x) * 2;
    if (e + 1 < E) {
        int c0, c1, s0, s1;
        load_idx2(ei, (size_t)E + e, c0, c1);
        load_idx2(ei, (size_t)e, s0, s1);
        if ((unsigned)c0 < (unsigned)N_NODES && (unsigned)s0 < (unsigned)N_NODES) {
            int p = atomicAdd(&g_cur[c0], 1);
            g_src[p] = s0;
            atomicAdd(&g_asum[c0], g_dinv[s0]);   // REDG, no return use
        }
        if ((unsigned)c1 < (unsigned)N_NODES && (unsigned)s1 < (unsigned)N_NODES) {
            int p = atomicAdd(&g_cur[c1], 1);
            g_src[p] = s1;
            atomicAdd(&g_asum[c1], g_dinv[s1]);
        }
    } else if (e < E) {
        int c = load_idx(ei, (size_t)E + e);
        int s = load_idx(ei, (size_t)e);
        if ((unsigned)c < (unsigned)N_NODES && (unsigned)s < (unsigned)N_NODES) {
            int p = atomicAdd(&g_cur[c], 1);
            g_src[p] = s;
            atomicAdd(&g_asum[c], g_dinv[s]);
        }
    }
}

// ------------------------------------------------------------------
// one block: Wc = W1 @ W2 (64x64x64) and bv = b1 @ W2
__global__ __launch_bounds__(256) void k_wc(
    const float* __restrict__ W1, const float* __restrict__ W2,
    const float* __restrict__ b1)
{
    __shared__ float w1s[64 * 64];
    __shared__ float w2s[64 * 64];
    int t = threadIdx.x;
    for (int i = t; i < 1024; i += 256) {
        ((float4*)w1s)[i] = ((const float4*)W1)[i];
        ((float4*)w2s)[i] = ((const float4*)W2)[i];
    }
    __syncthreads();
    int row = t >> 2;
    int cb  = (t & 3) * 16;
    float acc[16];
#pragma unroll
    for (int j = 0; j < 16; ++j) acc[j] = 0.f;
    for (int k = 0; k < 64; ++k) {
        float a = w1s[row * 64 + k];
#pragma unroll
        for (int j = 0; j < 16; ++j)
            acc[j] = fmaf(a, w2s[k * 64 + cb + j], acc[j]);
    }
#pragma unroll
    for (int j = 0; j < 16; ++j) g_Wc[row * 64 + cb + j] = acc[j];
    if (t < 64) {
        float s = 0.f;
        for (int k = 0; k < 64; ++k) s = fmaf(b1[k], w2s[k * 64 + t], s);
        g_bv[t] = s;
    }
}

// ------------------------------------------------------------------
// zs[i,:] = dinv[i] * x[i,:]  (coalesced; resolves user/item split once)
__global__ __launch_bounds__(256) void k_pre(
    const float* __restrict__ xa, const float* __restrict__ xb)
{
    int t = blockIdx.x * blockDim.x + threadIdx.x;
    int node = t >> 4;
    if (node >= N_NODES) return;
    int lane = (t & 15) * 4;
    const float* xrow = (node < N_USERS) ? (xa + (size_t)node * DIM)
                                         : (xb + (size_t)(node - N_USERS) * DIM);
    float dn = g_dinv[node];
    float4 v = *(const float4*)(xrow + lane);
    *(float4*)(g_z + (size_t)node * DIM + lane) =
        make_float4(dn * v.x, dn * v.y, dn * v.z, dn * v.w);
}

// ------------------------------------------------------------------
// hop 1: u1[c,:] = dinv^2[c] * (zs[c,:] + sum zs[src,:])   (g_z -> g_h)
//        + finalize a[c] = dinv[c]*(dinv[c]+asum[c])
__global__ __launch_bounds__(256) void k_agg1()
{
    int t = blockIdx.x * blockDim.x + threadIdx.x;
    int node = t >> 4;
    if (node >= N_NODES) return;
    int lane = (t & 15) * 4;

    float4 acc = *(const float4*)(g_z + (size_t)node * DIM + lane);  // self
    int s0 = g_off[node];
    int cnt = g_cur[node] - s0;
    for (int i = 0; i < cnt; ++i) {
        int src = g_src[s0 + i];
        float4 v = *(const float4*)(g_z + (size_t)src * DIM + lane);
        acc.x += v.x; acc.y += v.y; acc.z += v.z; acc.w += v.w;
    }
    float dn = g_dinv[node];
    float d2 = dn * dn;
    *(float4*)(g_h + (size_t)node * DIM + lane) =
        make_float4(d2 * acc.x, d2 * acc.y, d2 * acc.z, d2 * acc.w);
    if ((t & 15) == 0) g_a[node] = dn * (dn + g_asum[node]);
}

// hop 2: y2[c,:] = dinv[c] * (u1[c,:] + sum u1[src,:])   (g_h -> g_z)
__global__ __launch_bounds__(256) void k_agg2()
{
    int t = blockIdx.x * blockDim.x + threadIdx.x;
    int node = t >> 4;
    if (node >= N_NODES) return;
    int lane = (t & 15) * 4;

    float4 acc = *(const float4*)(g_h + (size_t)node * DIM + lane);  // self
    int s0 = g_off[node];
    int cnt = g_cur[node] - s0;
    for (int i = 0; i < cnt; ++i) {
        int src = g_src[s0 + i];
        float4 v = *(const float4*)(g_h + (size_t)src * DIM + lane);
        acc.x += v.x; acc.y += v.y; acc.z += v.z; acc.w += v.w;
    }
    float dn = g_dinv[node];
    *(float4*)(g_z + (size_t)node * DIM + lane) =
        make_float4(dn * acc.x, dn * acc.y, dn * acc.z, dn * acc.w);
}

// ------------------------------------------------------------------
// out[r,:] = y2[r,:] @ Wc + a[r]*bv + b2   (64 rows/block, 4x4 micro-tile)
__global__ __launch_bounds__(256) void k_gemm(
    const float* __restrict__ b2, float* __restrict__ out)
{
    __shared__ __align__(16) float Ws[64 * 64];
    __shared__ __align__(16) float xs[64][68];
    __shared__ float bvs[64], b2s[64];
    int tid = threadIdx.x;
    int block_row = blockIdx.x * 64;

    for (int i = tid; i < 1024; i += 256)
        ((float4*)Ws)[i] = ((const float4*)g_Wc)[i];
    if (tid < 64) { bvs[tid] = g_bv[tid]; b2s[tid] = b2[tid]; }

    {
        int r = tid >> 2;
        int kb = (tid & 3) * 16;
        const float* xrow = g_z + (size_t)(block_row + r) * DIM;
#pragma unroll
        for (int q = 0; q < 4; ++q)
            *(float4*)(&xs[r][kb + q * 4]) = *(const float4*)(xrow + kb + q * 4);
    }
    __syncthreads();

    int ty = tid >> 4, tx = tid & 15;
    float acc[4][4] = {};
#pragma unroll 16
    for (int k = 0; k < 64; ++k) {
        float4 wv = *(const float4*)(Ws + k * 64 + tx * 4);
#pragma unroll
        for (int i = 0; i < 4; ++i) {
            float xv = xs[ty * 4 + i][k];
            acc[i][0] = fmaf(xv, wv.x, acc[i][0]);
            acc[i][1] = fmaf(xv, wv.y, acc[i][1]);
            acc[i][2] = fmaf(xv, wv.z, acc[i][2]);
            acc[i][3] = fmaf(xv, wv.w, acc[i][3]);
        }
    }
    float4 bvv = *(const float4*)(bvs + tx * 4);
    float4 b2v = *(const float4*)(b2s + tx * 4);
#pragma unroll
    for (int i = 0; i < 4; ++i) {
        int gr = block_row + ty * 4 + i;
        float av = g_a[gr];
        float4 o = make_float4(
            fmaf(av, bvv.x, acc[i][0]) + b2v.x,
            fmaf(av, bvv.y, acc[i][1]) + b2v.y,
            fmaf(av, bvv.z, acc[i][2]) + b2v.z,
            fmaf(av, bvv.w, acc[i][3]) + b2v.w);
        *(float4*)(out + (size_t)gr * DIM + tx * 4) = o;
    }
}

// ------------------------------------------------------------------
extern "C" void kernel_launch(void* const* d_in, const int* in_sizes, int n_in,
                              void* d_out, int out_size)
{
    const void*  ei   = d_in[0];
    const float* user = (const float*)d_in[1];
    const float* item = (const float*)d_in[2];
    const float* W1   = (const float*)d_in[3];
    const float* b1   = (const float*)d_in[4];
    const float* W2   = (const float*)d_in[5];
    const float* b2   = (const float*)d_in[6];
    float* out        = (float*)d_out;
    int E = in_sizes[0] / 2;

    int zb  = (N_NODES + 255) / 256;
    int eb2 = (E / 2 + 255) / 256;

    // graph prep (every launch; kernels only -> graph-capturable)
    k_zero<<<zb, 256>>>((const unsigned int*)ei);
    k_hist<<<eb2, 256>>>(ei, E);
    k_scan1<<<NUM_SCAN_BLOCKS, 256>>>();
    k_scan2<<<1, 256>>>();
    k_scan3<<<zb, 256>>>();
    k_fill<<<eb2, 256>>>(ei, E);
    k_wc<<<1, 256>>>(W1, W2, b1);

    int node_blocks = (N_NODES * 16 + 255) / 256;   // 12500
    int gemm_blocks = N_NODES / 64;                 // 3125 (exact)

    k_pre<<<node_blocks, 256>>>(user, item);   // zs = dinv*x   -> g_z
    k_agg1<<<node_blocks, 256>>>();            // u1, a         -> g_h, g_a
    k_agg2<<<node_blocks, 256>>>();            // y2            -> g_z
    k_gemm<<<gemm_blocks, 256>>>(b2, out);     // out = y2 Wc + a bv + b2
}

// round 9
// speedup vs baseline: 1.5797x; 1.0964x over previous
#include <cuda_runtime.h>
#include <math.h>

#define N_NODES 200000
#define N_USERS 100000
#define DIM 64
#define E_MAX   1200000
#define NODES_PER_SCAN_BLK 1024
#define NUM_SCAN_BLOCKS ((N_NODES + NODES_PER_SCAN_BLK - 1) / NODES_PER_SCAN_BLK)  // 196

// ---- device scratch (static globals; no runtime allocation) ----
__device__ int   g_is64;
__device__ int   g_cnt[N_NODES];
__device__ int   g_off[N_NODES];
__device__ int   g_cur[N_NODES];
__device__ float g_dinv[N_NODES];
__device__ float g_asum[N_NODES];       // sum of dinv[src] per dest (REDG in fill)
__device__ float g_a[N_NODES];          // a = A_norm . 1
__device__ int   g_bsum[NUM_SCAN_BLOCKS];
__device__ int   g_src[E_MAX];
__device__ float g_Wc[64 * 64];         // W1 @ W2
__device__ float g_bv[64];              // b1 @ W2
__device__ float g_z[(size_t)N_NODES * DIM];   // zs = dinv * (x @ Wc)
__device__ float g_h[(size_t)N_NODES * DIM];   // u1 = dinv^2 (zs + gather)

// robust index fetch: edge_index may be int64 or int32 depending on JAX x64 config
__device__ __forceinline__ int load_idx(const void* ei, size_t pos) {
    if (g_is64) return (int)((const long long*)ei)[pos];
    return ((const int*)ei)[pos];
}
__device__ __forceinline__ void load_idx2(const void* ei, size_t pos, int& a, int& b) {
    if (g_is64) {
        longlong2 v = *(const longlong2*)((const long long*)ei + pos);
        a = (int)v.x; b = (int)v.y;
    } else {
        int2 v = *(const int2*)((const int*)ei + pos);
        a = v.x; b = v.y;
    }
}

// ------------------------------------------------------------------
// zero counters/asum + (block 0) detect edge dtype
__global__ void k_zero(const unsigned int* __restrict__ raw) {
    int i = blockIdx.x * blockDim.x + threadIdx.x;
    if (i < N_NODES) { g_cnt[i] = 0; g_asum[i] = 0.f; }
    if (blockIdx.x == 0) {
        __shared__ int any_hi;
        if (threadIdx.x == 0) any_hi = 0;
        __syncthreads();
        if (raw[threadIdx.x * 2 + 1] != 0u) any_hi = 1;  // benign race
        __syncthreads();
        if (threadIdx.x == 0) g_is64 = (any_hi == 0);
    }
}

// in-degree histogram over col = edge_index[1]; 2 edges per thread
__global__ void k_hist(const void* __restrict__ ei, int E) {
    int e = (blockIdx.x * blockDim.x + threadIdx.x) * 2;
    if (e + 1 < E) {
        int c0, c1;
        load_idx2(ei, (size_t)E + e, c0, c1);
        if ((unsigned)c0 < (unsigned)N_NODES) atomicAdd(&g_cnt[c0], 1);
        if ((unsigned)c1 < (unsigned)N_NODES) atomicAdd(&g_cnt[c1], 1);
    } else if (e < E) {
        int c = load_idx(ei, (size_t)E + e);
        if ((unsigned)c < (unsigned)N_NODES) atomicAdd(&g_cnt[c], 1);
    }
}

// ---- scan stage 1: per-1024-node block local scan + block totals ----
__global__ __launch_bounds__(256) void k_scan1() {
    __shared__ int sbuf[2][256];
    int t = threadIdx.x;
    int base = blockIdx.x * NODES_PER_SCAN_BLK + t * 4;
    int v[4]; int sum = 0;
#pragma unroll
    for (int q = 0; q < 4; ++q) {
        v[q] = (base + q < N_NODES) ? g_cnt[base + q] : 0;
        sum += v[q];
    }
    sbuf[0][t] = sum;
    __syncthreads();
    int cur = 0;
#pragma unroll
    for (int d = 1; d < 256; d <<= 1) {
        int x = sbuf[cur][t];
        if (t >= d) x += sbuf[cur][t - d];
        sbuf[1 - cur][t] = x;
        cur ^= 1;
        __syncthreads();
    }
    int incl = sbuf[cur][t];
    int excl = incl - sum;
#pragma unroll
    for (int q = 0; q < 4; ++q) {
        if (base + q < N_NODES) g_off[base + q] = excl;
        excl += v[q];
    }
    if (t == 255) g_bsum[blockIdx.x] = incl;
}

// ---- scan stage 2 (fused): every block re-scans the 196 partials in smem,
//      then finalizes offsets/cursors/dinv for its 256 nodes ----
__global__ __launch_bounds__(256) void k_scan3() {
    __shared__ int sbuf[2][256];
    __shared__ int pre[NUM_SCAN_BLOCKS];
    int t = threadIdx.x;
    int val = (t < NUM_SCAN_BLOCKS) ? g_bsum[t] : 0;
    sbuf[0][t] = val;
    __syncthreads();
    int cur = 0;
#pragma unroll
    for (int d = 1; d < 256; d <<= 1) {
        int x = sbuf[cur][t];
        if (t >= d) x += sbuf[cur][t - d];
        sbuf[1 - cur][t] = x;
        cur ^= 1;
        __syncthreads();
    }
    if (t < NUM_SCAN_BLOCKS) pre[t] = sbuf[cur][t] - val;
    __syncthreads();

    int idx = blockIdx.x * blockDim.x + t;
    if (idx < N_NODES) {
        int off = g_off[idx] + pre[idx / NODES_PER_SCAN_BLK];
        g_off[idx] = off;
        g_cur[idx] = off;
        g_dinv[idx] = rsqrtf((float)(g_cnt[idx] + 1));  // +1 self-loop
    }
}

// scatter srcs into dest-keyed CSR buckets + accumulate sum(dinv[src]) per dest
__global__ void k_fill(const void* __restrict__ ei, int E) {
    int e = (blockIdx.x * blockDim.x + threadIdx.x) * 2;
    if (e + 1 < E) {
        int c0, c1, s0, s1;
        load_idx2(ei, (size_t)E + e, c0, c1);
        load_idx2(ei, (size_t)e, s0, s1);
        if ((unsigned)c0 < (unsigned)N_NODES && (unsigned)s0 < (unsigned)N_NODES) {
            int p = atomicAdd(&g_cur[c0], 1);
            g_src[p] = s0;
            atomicAdd(&g_asum[c0], g_dinv[s0]);   // REDG, no return use
        }
        if ((unsigned)c1 < (unsigned)N_NODES && (unsigned)s1 < (unsigned)N_NODES) {
            int p = atomicAdd(&g_cur[c1], 1);
            g_src[p] = s1;
            atomicAdd(&g_asum[c1], g_dinv[s1]);
        }
    } else if (e < E) {
        int c = load_idx(ei, (size_t)E + e);
        int s = load_idx(ei, (size_t)e);
        if ((unsigned)c < (unsigned)N_NODES && (unsigned)s < (unsigned)N_NODES) {
            int p = atomicAdd(&g_cur[c], 1);
            g_src[p] = s;
            atomicAdd(&g_asum[c], g_dinv[s]);
        }
    }
}

// ------------------------------------------------------------------
// one block: Wc = W1 @ W2 (64x64x64) and bv = b1 @ W2
__global__ __launch_bounds__(256) void k_wc(
    const float* __restrict__ W1, const float* __restrict__ W2,
    const float* __restrict__ b1)
{
    __shared__ float w1s[64 * 64];
    __shared__ float w2s[64 * 64];
    int t = threadIdx.x;
    for (int i = t; i < 1024; i += 256) {
        ((float4*)w1s)[i] = ((const float4*)W1)[i];
        ((float4*)w2s)[i] = ((const float4*)W2)[i];
    }
    __syncthreads();
    int row = t >> 2;
    int cb  = (t & 3) * 16;
    float acc[16];
#pragma unroll
    for (int j = 0; j < 16; ++j) acc[j] = 0.f;
    for (int k = 0; k < 64; ++k) {
        float a = w1s[row * 64 + k];
#pragma unroll
        for (int j = 0; j < 16; ++j)
            acc[j] = fmaf(a, w2s[k * 64 + cb + j], acc[j]);
    }
#pragma unroll
    for (int j = 0; j < 16; ++j) g_Wc[row * 64 + cb + j] = acc[j];
    if (t < 64) {
        float s = 0.f;
        for (int k = 0; k < 64; ++k) s = fmaf(b1[k], w2s[k * 64 + t], s);
        g_bv[t] = s;
    }
}

// ------------------------------------------------------------------
// zs[r,:] = dinv[r] * (x[r,:] @ Wc)   (64 rows/block, 4x4 micro-tile)
// resolves the user/item split here; agg loops stay pure-add.
__global__ __launch_bounds__(256) void k_gemm(
    const float* __restrict__ xa, const float* __restrict__ xb)
{
    __shared__ __align__(16) float Ws[64 * 64];
    __shared__ __align__(16) float xs[64][68];
    int tid = threadIdx.x;
    int block_row = blockIdx.x * 64;

    for (int i = tid; i < 1024; i += 256)
        ((float4*)Ws)[i] = ((const float4*)g_Wc)[i];

    {
        int r = tid >> 2;
        int kb = (tid & 3) * 16;
        int gr = block_row + r;
        const float* xrow = (gr < N_USERS)
            ? (xa + (size_t)gr * DIM)
            : (xb + (size_t)(gr - N_USERS) * DIM);
#pragma unroll
        for (int q = 0; q < 4; ++q)
            *(float4*)(&xs[r][kb + q * 4]) = *(const float4*)(xrow + kb + q * 4);
    }
    __syncthreads();

    int ty = tid >> 4, tx = tid & 15;
    float acc[4][4] = {};
#pragma unroll 16
    for (int k = 0; k < 64; ++k) {
        float4 wv = *(const float4*)(Ws + k * 64 + tx * 4);
#pragma unroll
        for (int i = 0; i < 4; ++i) {
            float xv = xs[ty * 4 + i][k];
            acc[i][0] = fmaf(xv, wv.x, acc[i][0]);
            acc[i][1] = fmaf(xv, wv.y, acc[i][1]);
            acc[i][2] = fmaf(xv, wv.z, acc[i][2]);
            acc[i][3] = fmaf(xv, wv.w, acc[i][3]);
        }
    }
#pragma unroll
    for (int i = 0; i < 4; ++i) {
        int gr = block_row + ty * 4 + i;
        float s = g_dinv[gr];
        float4 o = make_float4(acc[i][0] * s, acc[i][1] * s,
                               acc[i][2] * s, acc[i][3] * s);
        *(float4*)(g_z + (size_t)gr * DIM + tx * 4) = o;
    }
}

// ------------------------------------------------------------------
// hop 1: u1[c,:] = dinv^2[c] * (zs[c,:] + sum zs[src,:])   (g_z -> g_h)
//        + finalize a[c] = dinv[c]*(dinv[c]+asum[c])
__global__ __launch_bounds__(256) void k_agg1()
{
    int t = blockIdx.x * blockDim.x + threadIdx.x;
    int node = t >> 4;
    if (node >= N_NODES) return;
    int lane = (t & 15) * 4;

    float4 acc = *(const float4*)(g_z + (size_t)node * DIM + lane);  // self
    int s0 = g_off[node];
    int cnt = g_cur[node] - s0;
    for (int i = 0; i < cnt; ++i) {
        int src = g_src[s0 + i];
        float4 v = *(const float4*)(g_z + (size_t)src * DIM + lane);
        acc.x += v.x; acc.y += v.y; acc.z += v.z; acc.w += v.w;
    }
    float dn = g_dinv[node];
    float d2 = dn * dn;
    *(float4*)(g_h + (size_t)node * DIM + lane) =
        make_float4(d2 * acc.x, d2 * acc.y, d2 * acc.z, d2 * acc.w);
    if ((t & 15) == 0) g_a[node] = dn * (dn + g_asum[node]);
}

// hop 2 + epilogue: out[c,:] = dinv[c]*(u1[c,:] + sum u1[src,:])
//                              + a[c]*bv + b2        (g_h -> d_out)
__global__ __launch_bounds__(256) void k_agg2(
    const float* __restrict__ b2, float* __restrict__ out)
{
    int t = blockIdx.x * blockDim.x + threadIdx.x;
    int node = t >> 4;
    if (node >= N_NODES) return;
    int lane = (t & 15) * 4;

    float4 acc = *(const float4*)(g_h + (size_t)node * DIM + lane);  // self
    int s0 = g_off[node];
    int cnt = g_cur[node] - s0;
    for (int i = 0; i < cnt; ++i) {
        int src = g_src[s0 + i];
        float4 v = *(const float4*)(g_h + (size_t)src * DIM + lane);
        acc.x += v.x; acc.y += v.y; acc.z += v.z; acc.w += v.w;
    }
    float dn = g_dinv[node];
    float av = g_a[node];
    float4 bvv = *(const float4*)(g_bv + lane);
    float4 b2v = *(const float4*)(b2 + lane);
    float4 o = make_float4(
        fmaf(dn, acc.x, fmaf(av, bvv.x, b2v.x)),
        fmaf(dn, acc.y, fmaf(av, bvv.y, b2v.y)),
        fmaf(dn, acc.z, fmaf(av, bvv.z, b2v.z)),
        fmaf(dn, acc.w, fmaf(av, bvv.w, b2v.w)));
    *(float4*)(out + (size_t)node * DIM + lane) = o;
}

// ------------------------------------------------------------------
extern "C" void kernel_launch(void* const* d_in, const int* in_sizes, int n_in,
                              void* d_out, int out_size)
{
    const void*  ei   = d_in[0];
    const float* user = (const float*)d_in[1];
    const float* item = (const float*)d_in[2];
    const float* W1   = (const float*)d_in[3];
    const float* b1   = (const float*)d_in[4];
    const float* W2   = (const float*)d_in[5];
    const float* b2   = (const float*)d_in[6];
    float* out        = (float*)d_out;
    int E = in_sizes[0] / 2;

    int zb  = (N_NODES + 255) / 256;
    int eb2 = (E / 2 + 255) / 256;

    // graph prep (every launch; kernels only -> graph-capturable)
    k_zero<<<zb, 256>>>((const unsigned int*)ei);
    k_hist<<<eb2, 256>>>(ei, E);
    k_scan1<<<NUM_SCAN_BLOCKS, 256>>>();
    k_scan3<<<zb, 256>>>();
    k_fill<<<eb2, 256>>>(ei, E);
    k_wc<<<1, 256>>>(W1, W2, b1);

    int node_blocks = (N_NODES * 16 + 255) / 256;   // 12500
    int gemm_blocks = N_NODES / 64;                 // 3125 (exact)

    k_gemm<<<gemm_blocks, 256>>>(user, item);  // zs = dinv*(x@Wc) -> g_z
    k_agg1<<<node_blocks, 256>>>();            // u1, a            -> g_h, g_a
    k_agg2<<<node_blocks, 256>>>(b2, out);     // out = A u1 + a*bv + b2
}

// round 10
// speedup vs baseline: 1.7235x; 1.0910x over previous
#include <cuda_runtime.h>
#include <math.h>

#define N_NODES 200000
#define N_USERS 100000
#define DIM 64
#define E_MAX   1200000
#define NODES_PER_SCAN_BLK 1024
#define NUM_SCAN_BLOCKS ((N_NODES + NODES_PER_SCAN_BLK - 1) / NODES_PER_SCAN_BLK)  // 196

// ---- device scratch (static globals; no runtime allocation) ----
__device__ int   g_is64;
__device__ int   g_cnt[N_NODES];
__device__ int   g_off[N_NODES];
__device__ int   g_cur[N_NODES];
__device__ float g_dinv[N_NODES];
__device__ float g_asum[N_NODES];       // sum of dinv[src] per dest (REDG in fill)
__device__ float g_a[N_NODES];          // a = A_norm . 1
__device__ int   g_bsum[NUM_SCAN_BLOCKS];
__device__ int   g_src[E_MAX];
__device__ float g_Wc[64 * 64];         // W1 @ W2
__device__ float g_bv[64];              // b1 @ W2
__device__ float g_z[(size_t)N_NODES * DIM];   // zs = dinv * (x @ Wc)
__device__ float g_h[(size_t)N_NODES * DIM];   // u1 = dinv^2 (zs + gather)

// robust index fetch: edge_index may be int64 or int32 depending on JAX x64 config
__device__ __forceinline__ int load_idx(const void* ei, size_t pos) {
    if (g_is64) return (int)((const long long*)ei)[pos];
    return ((const int*)ei)[pos];
}
__device__ __forceinline__ void load_idx2(const void* ei, size_t pos, int& a, int& b) {
    if (g_is64) {
        longlong2 v = *(const longlong2*)((const long long*)ei + pos);
        a = (int)v.x; b = (int)v.y;
    } else {
        int2 v = *(const int2*)((const int*)ei + pos);
        a = v.x; b = v.y;
    }
}

// ------------------------------------------------------------------
// zero counters/asum + (block 0) detect edge dtype
__global__ void k_zero(const unsigned int* __restrict__ raw) {
    int i = blockIdx.x * blockDim.x + threadIdx.x;
    if (i < N_NODES) { g_cnt[i] = 0; g_asum[i] = 0.f; }
    if (blockIdx.x == 0) {
        __shared__ int any_hi;
        if (threadIdx.x == 0) any_hi = 0;
        __syncthreads();
        if (raw[threadIdx.x * 2 + 1] != 0u) any_hi = 1;  // benign race
        __syncthreads();
        if (threadIdx.x == 0) g_is64 = (any_hi == 0);
    }
}

// in-degree histogram over col = edge_index[1]; 2 edges per thread
__global__ void k_hist(const void* __restrict__ ei, int E) {
    int e = (blockIdx.x * blockDim.x + threadIdx.x) * 2;
    if (e + 1 < E) {
        int c0, c1;
        load_idx2(ei, (size_t)E + e, c0, c1);
        if ((unsigned)c0 < (unsigned)N_NODES) atomicAdd(&g_cnt[c0], 1);
        if ((unsigned)c1 < (unsigned)N_NODES) atomicAdd(&g_cnt[c1], 1);
    } else if (e < E) {
        int c = load_idx(ei, (size_t)E + e);
        if ((unsigned)c < (unsigned)N_NODES) atomicAdd(&g_cnt[c], 1);
    }
}

// ---- scan stage 1: per-1024-node block local scan + block totals ----
__global__ __launch_bounds__(256) void k_scan1() {
    __shared__ int sbuf[2][256];
    int t = threadIdx.x;
    int base = blockIdx.x * NODES_PER_SCAN_BLK + t * 4;
    int v[4]; int sum = 0;
#pragma unroll
    for (int q = 0; q < 4; ++q) {
        v[q] = (base + q < N_NODES) ? g_cnt[base + q] : 0;
        sum += v[q];
    }
    sbuf[0][t] = sum;
    __syncthreads();
    int cur = 0;
#pragma unroll
    for (int d = 1; d < 256; d <<= 1) {
        int x = sbuf[cur][t];
        if (t >= d) x += sbuf[cur][t - d];
        sbuf[1 - cur][t] = x;
        cur ^= 1;
        __syncthreads();
    }
    int incl = sbuf[cur][t];
    int excl = incl - sum;
#pragma unroll
    for (int q = 0; q < 4; ++q) {
        if (base + q < N_NODES) g_off[base + q] = excl;
        excl += v[q];
    }
    if (t == 255) g_bsum[blockIdx.x] = incl;
}

// ---- scan stage 2 (fused): every block re-scans the 196 partials in smem,
//      then finalizes offsets/cursors/dinv for its 256 nodes ----
__global__ __launch_bounds__(256) void k_scan3() {
    __shared__ int sbuf[2][256];
    __shared__ int pre[NUM_SCAN_BLOCKS];
    int t = threadIdx.x;
    int val = (t < NUM_SCAN_BLOCKS) ? g_bsum[t] : 0;
    sbuf[0][t] = val;
    __syncthreads();
    int cur = 0;
#pragma unroll
    for (int d = 1; d < 256; d <<= 1) {
        int x = sbuf[cur][t];
        if (t >= d) x += sbuf[cur][t - d];
        sbuf[1 - cur][t] = x;
        cur ^= 1;
        __syncthreads();
    }
    if (t < NUM_SCAN_BLOCKS) pre[t] = sbuf[cur][t] - val;
    __syncthreads();

    int idx = blockIdx.x * blockDim.x + t;
    if (idx < N_NODES) {
        int off = g_off[idx] + pre[idx / NODES_PER_SCAN_BLK];
        g_off[idx] = off;
        g_cur[idx] = off;
        g_dinv[idx] = rsqrtf((float)(g_cnt[idx] + 1));  // +1 self-loop
    }
}

// scatter srcs into dest-keyed CSR buckets + accumulate sum(dinv[src]) per dest
__global__ void k_fill(const void* __restrict__ ei, int E) {
    int e = (blockIdx.x * blockDim.x + threadIdx.x) * 2;
    if (e + 1 < E) {
        int c0, c1, s0, s1;
        load_idx2(ei, (size_t)E + e, c0, c1);
        load_idx2(ei, (size_t)e, s0, s1);
        if ((unsigned)c0 < (unsigned)N_NODES && (unsigned)s0 < (unsigned)N_NODES) {
            int p = atomicAdd(&g_cur[c0], 1);
            g_src[p] = s0;
            atomicAdd(&g_asum[c0], g_dinv[s0]);   // REDG, no return use
        }
        if ((unsigned)c1 < (unsigned)N_NODES && (unsigned)s1 < (unsigned)N_NODES) {
            int p = atomicAdd(&g_cur[c1], 1);
            g_src[p] = s1;
            atomicAdd(&g_asum[c1], g_dinv[s1]);
        }
    } else if (e < E) {
        int c = load_idx(ei, (size_t)E + e);
        int s = load_idx(ei, (size_t)e);
        if ((unsigned)c < (unsigned)N_NODES && (unsigned)s < (unsigned)N_NODES) {
            int p = atomicAdd(&g_cur[c], 1);
            g_src[p] = s;
            atomicAdd(&g_asum[c], g_dinv[s]);
        }
    }
}

// ------------------------------------------------------------------
// one block: Wc = W1 @ W2 (64x64x64) and bv = b1 @ W2
__global__ __launch_bounds__(256) void k_wc(
    const float* __restrict__ W1, const float* __restrict__ W2,
    const float* __restrict__ b1)
{
    __shared__ float w1s[64 * 64];
    __shared__ float w2s[64 * 64];
    int t = threadIdx.x;
    for (int i = t; i < 1024; i += 256) {
        ((float4*)w1s)[i] = ((const float4*)W1)[i];
        ((float4*)w2s)[i] = ((const float4*)W2)[i];
    }
    __syncthreads();
    int row = t >> 2;
    int cb  = (t & 3) * 16;
    float acc[16];
#pragma unroll
    for (int j = 0; j < 16; ++j) acc[j] = 0.f;
    for (int k = 0; k < 64; ++k) {
        float a = w1s[row * 64 + k];
#pragma unroll
        for (int j = 0; j < 16; ++j)
            acc[j] = fmaf(a, w2s[k * 64 + cb + j], acc[j]);
    }
#pragma unroll
    for (int j = 0; j < 16; ++j) g_Wc[row * 64 + cb + j] = acc[j];
    if (t < 64) {
        float s = 0.f;
        for (int k = 0; k < 64; ++k) s = fmaf(b1[k], w2s[k * 64 + t], s);
        g_bv[t] = s;
    }
}

// ------------------------------------------------------------------
// zs[r,:] = dinv[r] * (x[r,:] @ Wc)   (64 rows/block, 4x4 micro-tile)
__global__ __launch_bounds__(256) void k_gemm(
    const float* __restrict__ xa, const float* __restrict__ xb)
{
    __shared__ __align__(16) float Ws[64 * 64];
    __shared__ __align__(16) float xs[64][68];
    int tid = threadIdx.x;
    int block_row = blockIdx.x * 64;

    for (int i = tid; i < 1024; i += 256)
        ((float4*)Ws)[i] = ((const float4*)g_Wc)[i];

    {
        int r = tid >> 2;
        int kb = (tid & 3) * 16;
        int gr = block_row + r;
        const float* xrow = (gr < N_USERS)
            ? (xa + (size_t)gr * DIM)
            : (xb + (size_t)(gr - N_USERS) * DIM);
#pragma unroll
        for (int q = 0; q < 4; ++q)
            *(float4*)(&xs[r][kb + q * 4]) = *(const float4*)(xrow + kb + q * 4);
    }
    __syncthreads();

    int ty = tid >> 4, tx = tid & 15;
    float acc[4][4] = {};
#pragma unroll 16
    for (int k = 0; k < 64; ++k) {
        float4 wv = *(const float4*)(Ws + k * 64 + tx * 4);
#pragma unroll
        for (int i = 0; i < 4; ++i) {
            float xv = xs[ty * 4 + i][k];
            acc[i][0] = fmaf(xv, wv.x, acc[i][0]);
            acc[i][1] = fmaf(xv, wv.y, acc[i][1]);
            acc[i][2] = fmaf(xv, wv.z, acc[i][2]);
            acc[i][3] = fmaf(xv, wv.w, acc[i][3]);
        }
    }
#pragma unroll
    for (int i = 0; i < 4; ++i) {
        int gr = block_row + ty * 4 + i;
        float s = g_dinv[gr];
        float4 o = make_float4(acc[i][0] * s, acc[i][1] * s,
                               acc[i][2] * s, acc[i][3] * s);
        *(float4*)(g_z + (size_t)gr * DIM + tx * 4) = o;
    }
}

// ------------------------------------------------------------------
// hop 1: u1[c,:] = dinv^2[c] * (zs[c,:] + sum zs[src,:])   (g_z -> g_h)
//        + finalize a[c] = dinv[c]*(dinv[c]+asum[c])
__global__ __launch_bounds__(256) void k_agg1()
{
    int t = blockIdx.x * blockDim.x + threadIdx.x;
    int node = t >> 4;
    if (node >= N_NODES) return;
    int lane = (t & 15) * 4;

    float4 acc = *(const float4*)(g_z + (size_t)node * DIM + lane);  // self
    int s0 = g_off[node];
    int cnt = g_cur[node] - s0;
    for (int i = 0; i < cnt; ++i) {
        int src = g_src[s0 + i];
        float4 v = *(const float4*)(g_z + (size_t)src * DIM + lane);
        acc.x += v.x; acc.y += v.y; acc.z += v.z; acc.w += v.w;
    }
    float dn = g_dinv[node];
    float d2 = dn * dn;
    *(float4*)(g_h + (size_t)node * DIM + lane) =
        make_float4(d2 * acc.x, d2 * acc.y, d2 * acc.z, d2 * acc.w);
    if ((t & 15) == 0) g_a[node] = dn * (dn + g_asum[node]);
}

// hop 2 + epilogue: out[c,:] = dinv[c]*(u1[c,:] + sum u1[src,:])
//                              + a[c]*bv + b2        (g_h -> d_out)
__global__ __launch_bounds__(256) void k_agg2(
    const float* __restrict__ b2, float* __restrict__ out)
{
    int t = blockIdx.x * blockDim.x + threadIdx.x;
    int node = t >> 4;
    if (node >= N_NODES) return;
    int lane = (t & 15) * 4;

    float4 acc = *(const float4*)(g_h + (size_t)node * DIM + lane);  // self
    int s0 = g_off[node];
    int cnt = g_cur[node] - s0;
    for (int i = 0; i < cnt; ++i) {
        int src = g_src[s0 + i];
        float4 v = *(const float4*)(g_h + (size_t)src * DIM + lane);
        acc.x += v.x; acc.y += v.y; acc.z += v.z; acc.w += v.w;
    }
    float dn = g_dinv[node];
    float av = g_a[node];
    float4 bvv = *(const float4*)(g_bv + lane);
    float4 b2v = *(const float4*)(b2 + lane);
    float4 o = make_float4(
        fmaf(dn, acc.x, fmaf(av, bvv.x, b2v.x)),
        fmaf(dn, acc.y, fmaf(av, bvv.y, b2v.y)),
        fmaf(dn, acc.z, fmaf(av, bvv.z, b2v.z)),
        fmaf(dn, acc.w, fmaf(av, bvv.w, b2v.w)));
    *(float4*)(out + (size_t)node * DIM + lane) = o;
}

// ------------------------------------------------------------------
extern "C" void kernel_launch(void* const* d_in, const int* in_sizes, int n_in,
                              void* d_out, int out_size)
{
    const void*  ei   = d_in[0];
    const float* user = (const float*)d_in[1];
    const float* item = (const float*)d_in[2];
    const float* W1   = (const float*)d_in[3];
    const float* b1   = (const float*)d_in[4];
    const float* W2   = (const float*)d_in[5];
    const float* b2   = (const float*)d_in[6];
    float* out        = (float*)d_out;
    int E = in_sizes[0] / 2;

    int zb  = (N_NODES + 255) / 256;
    int eb2 = (E / 2 + 255) / 256;
    int node_blocks = (N_NODES * 16 + 255) / 256;   // 12500
    int gemm_blocks = N_NODES / 64;                 // 3125 (exact)

    // one-time infra (created on the first, non-captured, correctness call;
    // no device memory is allocated by streams/events)
    static cudaStream_t s_aux = nullptr;
    static cudaEvent_t ev_fork = nullptr, ev_wc = nullptr, ev_fill = nullptr,
                       ev_scan = nullptr;
    if (s_aux == nullptr) {
        cudaStreamCreateWithFlags(&s_aux, cudaStreamNonBlocking);
        cudaEventCreateWithFlags(&ev_fork, cudaEventDisableTiming);
        cudaEventCreateWithFlags(&ev_wc,   cudaEventDisableTiming);
        cudaEventCreateWithFlags(&ev_fill, cudaEventDisableTiming);
        cudaEventCreateWithFlags(&ev_scan, cudaEventDisableTiming);
    }

    // fork: aux stream computes Wc (independent of graph prep)
    cudaEventRecord(ev_fork, 0);
    cudaStreamWaitEvent(s_aux, ev_fork, 0);
    k_wc<<<1, 256, 0, s_aux>>>(W1, W2, b1);
    cudaEventRecord(ev_wc, s_aux);

    // main stream: graph prep chain
    k_zero<<<zb, 256>>>((const unsigned int*)ei);
    k_hist<<<eb2, 256>>>(ei, E);
    k_scan1<<<NUM_SCAN_BLOCKS, 256>>>();
    k_scan3<<<zb, 256>>>();

    // fork: fill (L2/atomic-bound) runs on aux concurrently with gemm (FMA-bound)
    cudaEventRecord(ev_scan, 0);
    cudaStreamWaitEvent(s_aux, ev_scan, 0);
    k_fill<<<eb2, 256, 0, s_aux>>>(ei, E);
    cudaEventRecord(ev_fill, s_aux);

    cudaStreamWaitEvent(0, ev_wc, 0);          // gemm needs Wc + dinv
    k_gemm<<<gemm_blocks, 256>>>(user, item);  // zs = dinv*(x@Wc) -> g_z

    // join: aggregation needs both gemm (main) and fill (aux)
    cudaStreamWaitEvent(0, ev_fill, 0);
    k_agg1<<<node_blocks, 256>>>();            // u1, a -> g_h, g_a
    k_agg2<<<node_blocks, 256>>>(b2, out);     // out = A u1 + a*bv + b2
}

// round 11
// speedup vs baseline: 1.9588x; 1.1365x over previous
#include <cuda_runtime.h>
#include <cuda_fp16.h>
#include <math.h>

#define N_NODES 200000
#define N_USERS 100000
#define DIM 64
#define E_MAX   1200000
#define NODES_PER_SCAN_BLK 1024
#define NUM_SCAN_BLOCKS ((N_NODES + NODES_PER_SCAN_BLK - 1) / NODES_PER_SCAN_BLK)  // 196

// ---- device scratch (static globals; no runtime allocation) ----
__device__ int   g_is64;
__device__ int   g_cnt[N_NODES];
__device__ int   g_off[N_NODES];
__device__ int   g_cur[N_NODES];
__device__ float g_dinv[N_NODES];
__device__ float g_asum[N_NODES];       // sum of dinv[src] per dest (REDG in fill)
__device__ float g_a[N_NODES];          // a = A_norm . 1
__device__ int   g_bsum[NUM_SCAN_BLOCKS];
__device__ int   g_src[E_MAX];
__device__ float g_Wc[64 * 64];         // W1 @ W2
__device__ float g_bv[64];              // b1 @ W2
__device__ __half g_zh[(size_t)N_NODES * DIM];  // zs = dinv*(x@Wc), fp16
__device__ __half g_hh[(size_t)N_NODES * DIM];  // u1, fp16

// robust index fetch: edge_index may be int64 or int32 depending on JAX x64 config
__device__ __forceinline__ int load_idx(const void* ei, size_t pos) {
    if (g_is64) return (int)((const long long*)ei)[pos];
    return ((const int*)ei)[pos];
}
__device__ __forceinline__ void load_idx2(const void* ei, size_t pos, int& a, int& b) {
    if (g_is64) {
        longlong2 v = *(const longlong2*)((const long long*)ei + pos);
        a = (int)v.x; b = (int)v.y;
    } else {
        int2 v = *(const int2*)((const int*)ei + pos);
        a = v.x; b = v.y;
    }
}

// accumulate 8 halves (uint4) into 8 fp32 accumulators
__device__ __forceinline__ void h8_add(float* acc, uint4 v) {
    float2 f;
    f = __half22float2(*(__half2*)&v.x); acc[0] += f.x; acc[1] += f.y;
    f = __half22float2(*(__half2*)&v.y); acc[2] += f.x; acc[3] += f.y;
    f = __half22float2(*(__half2*)&v.z); acc[4] += f.x; acc[5] += f.y;
    f = __half22float2(*(__half2*)&v.w); acc[6] += f.x; acc[7] += f.y;
}

// ------------------------------------------------------------------
// zero counters/asum + (block 0) detect edge dtype
__global__ void k_zero(const unsigned int* __restrict__ raw) {
    int i = blockIdx.x * blockDim.x + threadIdx.x;
    if (i < N_NODES) { g_cnt[i] = 0; g_asum[i] = 0.f; }
    if (blockIdx.x == 0) {
        __shared__ int any_hi;
        if (threadIdx.x == 0) any_hi = 0;
        __syncthreads();
        if (raw[threadIdx.x * 2 + 1] != 0u) any_hi = 1;  // benign race
        __syncthreads();
        if (threadIdx.x == 0) g_is64 = (any_hi == 0);
    }
}

// in-degree histogram over col = edge_index[1]; 2 edges per thread
__global__ void k_hist(const void* __restrict__ ei, int E) {
    int e = (blockIdx.x * blockDim.x + threadIdx.x) * 2;
    if (e + 1 < E) {
        int c0, c1;
        load_idx2(ei, (size_t)E + e, c0, c1);
        if ((unsigned)c0 < (unsigned)N_NODES) atomicAdd(&g_cnt[c0], 1);
        if ((unsigned)c1 < (unsigned)N_NODES) atomicAdd(&g_cnt[c1], 1);
    } else if (e < E) {
        int c = load_idx(ei, (size_t)E + e);
        if ((unsigned)c < (unsigned)N_NODES) atomicAdd(&g_cnt[c], 1);
    }
}

// ---- scan stage 1: per-1024-node block local scan + block totals ----
__global__ __launch_bounds__(256) void k_scan1() {
    __shared__ int sbuf[2][256];
    int t = threadIdx.x;
    int base = blockIdx.x * NODES_PER_SCAN_BLK + t * 4;
    int v[4]; int sum = 0;
#pragma unroll
    for (int q = 0; q < 4; ++q) {
        v[q] = (base + q < N_NODES) ? g_cnt[base + q] : 0;
        sum += v[q];
    }
    sbuf[0][t] = sum;
    __syncthreads();
    int cur = 0;
#pragma unroll
    for (int d = 1; d < 256; d <<= 1) {
        int x = sbuf[cur][t];
        if (t >= d) x += sbuf[cur][t - d];
        sbuf[1 - cur][t] = x;
        cur ^= 1;
        __syncthreads();
    }
    int incl = sbuf[cur][t];
    int excl = incl - sum;
#pragma unroll
    for (int q = 0; q < 4; ++q) {
        if (base + q < N_NODES) g_off[base + q] = excl;
        excl += v[q];
    }
    if (t == 255) g_bsum[blockIdx.x] = incl;
}

// ---- scan stage 2 (fused): every block re-scans the 196 partials in smem,
//      then finalizes offsets/cursors/dinv for its 256 nodes ----
__global__ __launch_bounds__(256) void k_scan3() {
    __shared__ int sbuf[2][256];
    __shared__ int pre[NUM_SCAN_BLOCKS];
    int t = threadIdx.x;
    int val = (t < NUM_SCAN_BLOCKS) ? g_bsum[t] : 0;
    sbuf[0][t] = val;
    __syncthreads();
    int cur = 0;
#pragma unroll
    for (int d = 1; d < 256; d <<= 1) {
        int x = sbuf[cur][t];
        if (t >= d) x += sbuf[cur][t - d];
        sbuf[1 - cur][t] = x;
        cur ^= 1;
        __syncthreads();
    }
    if (t < NUM_SCAN_BLOCKS) pre[t] = sbuf[cur][t] - val;
    __syncthreads();

    int idx = blockIdx.x * blockDim.x + t;
    if (idx < N_NODES) {
        int off = g_off[idx] + pre[idx / NODES_PER_SCAN_BLK];
        g_off[idx] = off;
        g_cur[idx] = off;
        g_dinv[idx] = rsqrtf((float)(g_cnt[idx] + 1));  // +1 self-loop
    }
}

// scatter srcs into dest-keyed CSR buckets + accumulate sum(dinv[src]) per dest
__global__ void k_fill(const void* __restrict__ ei, int E) {
    int e = (blockIdx.x * blockDim.x + threadIdx.x) * 2;
    if (e + 1 < E) {
        int c0, c1, s0, s1;
        load_idx2(ei, (size_t)E + e, c0, c1);
        load_idx2(ei, (size_t)e, s0, s1);
        if ((unsigned)c0 < (unsigned)N_NODES && (unsigned)s0 < (unsigned)N_NODES) {
            int p = atomicAdd(&g_cur[c0], 1);
            g_src[p] = s0;
            atomicAdd(&g_asum[c0], g_dinv[s0]);   // REDG, no return use
        }
        if ((unsigned)c1 < (unsigned)N_NODES && (unsigned)s1 < (unsigned)N_NODES) {
            int p = atomicAdd(&g_cur[c1], 1);
            g_src[p] = s1;
            atomicAdd(&g_asum[c1], g_dinv[s1]);
        }
    } else if (e < E) {
        int c = load_idx(ei, (size_t)E + e);
        int s = load_idx(ei, (size_t)e);
        if ((unsigned)c < (unsigned)N_NODES && (unsigned)s < (unsigned)N_NODES) {
            int p = atomicAdd(&g_cur[c], 1);
            g_src[p] = s;
            atomicAdd(&g_asum[c], g_dinv[s]);
        }
    }
}

// ------------------------------------------------------------------
// one block: Wc = W1 @ W2 (64x64x64) and bv = b1 @ W2
__global__ __launch_bounds__(256) void k_wc(
    const float* __restrict__ W1, const float* __restrict__ W2,
    const float* __restrict__ b1)
{
    __shared__ float w1s[64 * 64];
    __shared__ float w2s[64 * 64];
    int t = threadIdx.x;
    for (int i = t; i < 1024; i += 256) {
        ((float4*)w1s)[i] = ((const float4*)W1)[i];
        ((float4*)w2s)[i] = ((const float4*)W2)[i];
    }
    __syncthreads();
    int row = t >> 2;
    int cb  = (t & 3) * 16;
    float acc[16];
#pragma unroll
    for (int j = 0; j < 16; ++j) acc[j] = 0.f;
    for (int k = 0; k < 64; ++k) {
        float a = w1s[row * 64 + k];
#pragma unroll
        for (int j = 0; j < 16; ++j)
            acc[j] = fmaf(a, w2s[k * 64 + cb + j], acc[j]);
    }
#pragma unroll
    for (int j = 0; j < 16; ++j) g_Wc[row * 64 + cb + j] = acc[j];
    if (t < 64) {
        float s = 0.f;
        for (int k = 0; k < 64; ++k) s = fmaf(b1[k], w2s[k * 64 + t], s);
        g_bv[t] = s;
    }
}

// ------------------------------------------------------------------
// zs[r,:] = dinv[r] * (x[r,:] @ Wc)  -> fp16 g_zh   (64 rows/block)
__global__ __launch_bounds__(256) void k_gemm(
    const float* __restrict__ xa, const float* __restrict__ xb)
{
    __shared__ __align__(16) float Ws[64 * 64];
    __shared__ __align__(16) float xs[64][68];
    int tid = threadIdx.x;
    int block_row = blockIdx.x * 64;

    for (int i = tid; i < 1024; i += 256)
        ((float4*)Ws)[i] = ((const float4*)g_Wc)[i];

    {
        int r = tid >> 2;
        int kb = (tid & 3) * 16;
        int gr = block_row + r;
        const float* xrow = (gr < N_USERS)
            ? (xa + (size_t)gr * DIM)
            : (xb + (size_t)(gr - N_USERS) * DIM);
#pragma unroll
        for (int q = 0; q < 4; ++q)
            *(float4*)(&xs[r][kb + q * 4]) = *(const float4*)(xrow + kb + q * 4);
    }
    __syncthreads();

    int ty = tid >> 4, tx = tid & 15;
    float acc[4][4] = {};
#pragma unroll 16
    for (int k = 0; k < 64; ++k) {
        float4 wv = *(const float4*)(Ws + k * 64 + tx * 4);
#pragma unroll
        for (int i = 0; i < 4; ++i) {
            float xv = xs[ty * 4 + i][k];
            acc[i][0] = fmaf(xv, wv.x, acc[i][0]);
            acc[i][1] = fmaf(xv, wv.y, acc[i][1]);
            acc[i][2] = fmaf(xv, wv.z, acc[i][2]);
            acc[i][3] = fmaf(xv, wv.w, acc[i][3]);
        }
    }
#pragma unroll
    for (int i = 0; i < 4; ++i) {
        int gr = block_row + ty * 4 + i;
        float s = g_dinv[gr];
        __half2 h0 = __floats2half2_rn(acc[i][0] * s, acc[i][1] * s);
        __half2 h1 = __floats2half2_rn(acc[i][2] * s, acc[i][3] * s);
        uint2 val;
        val.x = *(unsigned int*)&h0;
        val.y = *(unsigned int*)&h1;
        *(uint2*)(g_zh + (size_t)gr * DIM + tx * 4) = val;
    }
}

// ------------------------------------------------------------------
// hop 1: u1[c,:] = dinv^2[c] * (zs[c,:] + sum zs[src,:])   (g_zh -> g_hh)
//        + finalize a[c] = dinv[c]*(dinv[c]+asum[c])
// 8 threads per node, 8 halves (16B) per thread; fp32 accumulation
__global__ __launch_bounds__(256) void k_agg1()
{
    int t = blockIdx.x * blockDim.x + threadIdx.x;
    int node = t >> 3;
    if (node >= N_NODES) return;
    int lane = (t & 7) * 8;   // half index within row

    float acc[8] = {0.f, 0.f, 0.f, 0.f, 0.f, 0.f, 0.f, 0.f};
    h8_add(acc, *(const uint4*)(g_zh + (size_t)node * DIM + lane));  // self
    int s0 = g_off[node];
    int cnt = g_cur[node] - s0;
    for (int i = 0; i < cnt; ++i) {
        int src = g_src[s0 + i];
        h8_add(acc, *(const uint4*)(g_zh + (size_t)src * DIM + lane));
    }
    float dn = g_dinv[node];
    float d2 = dn * dn;
    __half2 h0 = __floats2half2_rn(d2 * acc[0], d2 * acc[1]);
    __half2 h1 = __floats2half2_rn(d2 * acc[2], d2 * acc[3]);
    __half2 h2 = __floats2half2_rn(d2 * acc[4], d2 * acc[5]);
    __half2 h3 = __floats2half2_rn(d2 * acc[6], d2 * acc[7]);
    uint4 val;
    val.x = *(unsigned int*)&h0; val.y = *(unsigned int*)&h1;
    val.z = *(unsigned int*)&h2; val.w = *(unsigned int*)&h3;
    *(uint4*)(g_hh + (size_t)node * DIM + lane) = val;
    if ((t & 7) == 0) g_a[node] = dn * (dn + g_asum[node]);
}

// hop 2 + epilogue: out[c,:] = dinv[c]*(u1[c,:] + sum u1[src,:])
//                              + a[c]*bv + b2        (g_hh -> d_out fp32)
__global__ __launch_bounds__(256) void k_agg2(
    const float* __restrict__ b2, float* __restrict__ out)
{
    int t = blockIdx.x * blockDim.x + threadIdx.x;
    int node = t >> 3;
    if (node >= N_NODES) return;
    int lane = (t & 7) * 8;

    float acc[8] = {0.f, 0.f, 0.f, 0.f, 0.f, 0.f, 0.f, 0.f};
    h8_add(acc, *(const uint4*)(g_hh + (size_t)node * DIM + lane));  // self
    int s0 = g_off[node];
    int cnt = g_cur[node] - s0;
    for (int i = 0; i < cnt; ++i) {
        int src = g_src[s0 + i];
        h8_add(acc, *(const uint4*)(g_hh + (size_t)src * DIM + lane));
    }
    float dn = g_dinv[node];
    float av = g_a[node];
    float4 bv0 = *(const float4*)(g_bv + lane);
    float4 bv1 = *(const float4*)(g_bv + lane + 4);
    float4 b20 = *(const float4*)(b2 + lane);
    float4 b21 = *(const float4*)(b2 + lane + 4);
    float* dst = out + (size_t)node * DIM + lane;
    float4 o0 = make_float4(
        fmaf(dn, acc[0], fmaf(av, bv0.x, b20.x)),
        fmaf(dn, acc[1], fmaf(av, bv0.y, b20.y)),
        fmaf(dn, acc[2], fmaf(av, bv0.z, b20.z)),
        fmaf(dn, acc[3], fmaf(av, bv0.w, b20.w)));
    float4 o1 = make_float4(
        fmaf(dn, acc[4], fmaf(av, bv1.x, b21.x)),
        fmaf(dn, acc[5], fmaf(av, bv1.y, b21.y)),
        fmaf(dn, acc[6], fmaf(av, bv1.z, b21.z)),
        fmaf(dn, acc[7], fmaf(av, bv1.w, b21.w)));
    *(float4*)dst       = o0;
    *(float4*)(dst + 4) = o1;
}

// ------------------------------------------------------------------
extern "C" void kernel_launch(void* const* d_in, const int* in_sizes, int n_in,
                              void* d_out, int out_size)
{
    const void*  ei   = d_in[0];
    const float* user = (const float*)d_in[1];
    const float* item = (const float*)d_in[2];
    const float* W1   = (const float*)d_in[3];
    const float* b1   = (const float*)d_in[4];
    const float* W2   = (const float*)d_in[5];
    const float* b2   = (const float*)d_in[6];
    float* out        = (float*)d_out;
    int E = in_sizes[0] / 2;

    int zb  = (N_NODES + 255) / 256;
    int eb2 = (E / 2 + 255) / 256;
    int agg_blocks  = (N_NODES * 8 + 255) / 256;    // 6250
    int gemm_blocks = N_NODES / 64;                 // 3125 (exact)

    // one-time infra (created on the first, non-captured, correctness call)
    static cudaStream_t s_aux = nullptr;
    static cudaEvent_t ev_fork = nullptr, ev_wc = nullptr, ev_fill = nullptr,
                       ev_scan = nullptr;
    if (s_aux == nullptr) {
        cudaStreamCreateWithFlags(&s_aux, cudaStreamNonBlocking);
        cudaEventCreateWithFlags(&ev_fork, cudaEventDisableTiming);
        cudaEventCreateWithFlags(&ev_wc,   cudaEventDisableTiming);
        cudaEventCreateWithFlags(&ev_fill, cudaEventDisableTiming);
        cudaEventCreateWithFlags(&ev_scan, cudaEventDisableTiming);
    }

    // fork: aux stream computes Wc (independent of graph prep)
    cudaEventRecord(ev_fork, 0);
    cudaStreamWaitEvent(s_aux, ev_fork, 0);
    k_wc<<<1, 256, 0, s_aux>>>(W1, W2, b1);
    cudaEventRecord(ev_wc, s_aux);

    // main stream: graph prep chain
    k_zero<<<zb, 256>>>((const unsigned int*)ei);
    k_hist<<<eb2, 256>>>(ei, E);
    k_scan1<<<NUM_SCAN_BLOCKS, 256>>>();
    k_scan3<<<zb, 256>>>();

    // fork: fill (L2/atomic-bound) runs concurrently with gemm (FMA-bound)
    cudaEventRecord(ev_scan, 0);
    cudaStreamWaitEvent(s_aux, ev_scan, 0);
    k_fill<<<eb2, 256, 0, s_aux>>>(ei, E);
    cudaEventRecord(ev_fill, s_aux);

    cudaStreamWaitEvent(0, ev_wc, 0);          // gemm needs Wc + dinv
    k_gemm<<<gemm_blocks, 256>>>(user, item);  // zs (fp16) -> g_zh

    // join: aggregation needs both gemm (main) and fill (aux)
    cudaStreamWaitEvent(0, ev_fill, 0);
    k_agg1<<<agg_blocks, 256>>>();             // u1 (fp16), a
    k_agg2<<<agg_blocks, 256>>>(b2, out);      // out = A u1 + a*bv + b2
}

// round 12
// speedup vs baseline: 2.5396x; 1.2965x over previous
#include <cuda_runtime.h>
#include <cuda_fp16.h>
#include <math.h>

#define N_NODES 200000
#define N_USERS 100000
#define DIM 64
#define E_MAX   1200000
#define NODES_PER_SCAN_BLK 1024
#define NUM_SCAN_BLOCKS ((N_NODES + NODES_PER_SCAN_BLK - 1) / NODES_PER_SCAN_BLK)  // 196
#define GEMM_ROWS 128

// ---- device scratch (static globals; zero-initialized at module load) ----
__device__ int   g_cnt[N_NODES];        // zeroed by scan3 of the SAME launch after use
__device__ int   g_off[N_NODES];
__device__ int   g_cur[N_NODES];
__device__ float g_dinv[N_NODES];
__device__ float g_a[N_NODES];          // a = A_norm . 1
__device__ int   g_bsum[NUM_SCAN_BLOCKS];
__device__ int   g_src[E_MAX];
__device__ __half g_Wch[64 * 64];       // (W1@W2)^T in fp16, layout [n][k]
__device__ float  g_bv[64];             // b1 @ W2
__device__ __half g_zh[(size_t)N_NODES * DIM];  // zs = dinv*(x@Wc), fp16
__device__ __half g_hh[(size_t)N_NODES * DIM];  // u1, fp16

// per-block dtype detection: int64 edge entries have zero hi-words.
// requires blockDim.x == 256 and E >= 256.
__device__ __forceinline__ int detect_is64(const unsigned int* raw) {
    __shared__ int s_hi;
    if (threadIdx.x == 0) s_hi = 0;
    __syncthreads();
    if (raw[threadIdx.x * 2 + 1] != 0u) s_hi = 1;   // benign race
    __syncthreads();
    return s_hi == 0;
}

__device__ __forceinline__ int load_idx(const void* ei, size_t pos, int is64) {
    if (is64) return (int)((const long long*)ei)[pos];
    return ((const int*)ei)[pos];
}
__device__ __forceinline__ void load_idx2(const void* ei, size_t pos, int is64,
                                          int& a, int& b) {
    if (is64) {
        longlong2 v = *(const longlong2*)((const long long*)ei + pos);
        a = (int)v.x; b = (int)v.y;
    } else {
        int2 v = *(const int2*)((const int*)ei + pos);
        a = v.x; b = v.y;
    }
}

// accumulate 8 halves (uint4) into 8 fp32 accumulators
__device__ __forceinline__ void h8_add(float* acc, uint4 v) {
    float2 f;
    f = __half22float2(*(__half2*)&v.x); acc[0] += f.x; acc[1] += f.y;
    f = __half22float2(*(__half2*)&v.y); acc[2] += f.x; acc[3] += f.y;
    f = __half22float2(*(__half2*)&v.z); acc[4] += f.x; acc[5] += f.y;
    f = __half22float2(*(__half2*)&v.w); acc[6] += f.x; acc[7] += f.y;
}

// ------------------------------------------------------------------
// in-degree histogram over col = edge_index[1]; 2 edges per thread
// (g_cnt arrives zeroed: module-load init on call 1, scan3 self-clean after)
__global__ __launch_bounds__(256) void k_hist(const void* __restrict__ ei, int E) {
    int is64 = detect_is64((const unsigned int*)ei);
    int e = (blockIdx.x * blockDim.x + threadIdx.x) * 2;
    if (e + 1 < E) {
        int c0, c1;
        load_idx2(ei, (size_t)E + e, is64, c0, c1);
        if ((unsigned)c0 < (unsigned)N_NODES) atomicAdd(&g_cnt[c0], 1);
        if ((unsigned)c1 < (unsigned)N_NODES) atomicAdd(&g_cnt[c1], 1);
    } else if (e < E) {
        int c = load_idx(ei, (size_t)E + e, is64);
        if ((unsigned)c < (unsigned)N_NODES) atomicAdd(&g_cnt[c], 1);
    }
}

// ---- scan stage 1: per-1024-node block local scan + block totals ----
__global__ __launch_bounds__(256) void k_scan1() {
    __shared__ int sbuf[2][256];
    int t = threadIdx.x;
    int base = blockIdx.x * NODES_PER_SCAN_BLK + t * 4;
    int v[4]; int sum = 0;
#pragma unroll
    for (int q = 0; q < 4; ++q) {
        v[q] = (base + q < N_NODES) ? g_cnt[base + q] : 0;
        sum += v[q];
    }
    sbuf[0][t] = sum;
    __syncthreads();
    int cur = 0;
#pragma unroll
    for (int d = 1; d < 256; d <<= 1) {
        int x = sbuf[cur][t];
        if (t >= d) x += sbuf[cur][t - d];
        sbuf[1 - cur][t] = x;
        cur ^= 1;
        __syncthreads();
    }
    int incl = sbuf[cur][t];
    int excl = incl - sum;
#pragma unroll
    for (int q = 0; q < 4; ++q) {
        if (base + q < N_NODES) g_off[base + q] = excl;
        excl += v[q];
    }
    if (t == 255) g_bsum[blockIdx.x] = incl;
}

// ---- scan stage 2 (fused): re-scan 196 partials per block, finalize
//      offsets/cursors/dinv, then self-clean g_cnt for the next launch ----
__global__ __launch_bounds__(256) void k_scan3() {
    __shared__ int sbuf[2][256];
    __shared__ int pre[NUM_SCAN_BLOCKS];
    int t = threadIdx.x;
    int val = (t < NUM_SCAN_BLOCKS) ? g_bsum[t] : 0;
    sbuf[0][t] = val;
    __syncthreads();
    int cur = 0;
#pragma unroll
    for (int d = 1; d < 256; d <<= 1) {
        int x = sbuf[cur][t];
        if (t >= d) x += sbuf[cur][t - d];
        sbuf[1 - cur][t] = x;
        cur ^= 1;
        __syncthreads();
    }
    if (t < NUM_SCAN_BLOCKS) pre[t] = sbuf[cur][t] - val;
    __syncthreads();

    int idx = blockIdx.x * blockDim.x + t;
    if (idx < N_NODES) {
        int cnt = g_cnt[idx];
        int off = g_off[idx] + pre[idx / NODES_PER_SCAN_BLK];
        g_off[idx] = off;
        g_cur[idx] = off;
        g_dinv[idx] = rsqrtf((float)(cnt + 1));  // +1 self-loop
        g_cnt[idx] = 0;                          // self-clean for next launch
    }
}

// scatter srcs into dest-keyed CSR buckets
__global__ __launch_bounds__(256) void k_fill(const void* __restrict__ ei, int E) {
    int is64 = detect_is64((const unsigned int*)ei);
    int e = (blockIdx.x * blockDim.x + threadIdx.x) * 2;
    if (e + 1 < E) {
        int c0, c1, s0, s1;
        load_idx2(ei, (size_t)E + e, is64, c0, c1);
        load_idx2(ei, (size_t)e, is64, s0, s1);
        if ((unsigned)c0 < (unsigned)N_NODES && (unsigned)s0 < (unsigned)N_NODES) {
            int p = atomicAdd(&g_cur[c0], 1);
            g_src[p] = s0;
        }
        if ((unsigned)c1 < (unsigned)N_NODES && (unsigned)s1 < (unsigned)N_NODES) {
            int p = atomicAdd(&g_cur[c1], 1);
            g_src[p] = s1;
        }
    } else if (e < E) {
        int c = load_idx(ei, (size_t)E + e, is64);
        int s = load_idx(ei, (size_t)e, is64);
        if ((unsigned)c < (unsigned)N_NODES && (unsigned)s < (unsigned)N_NODES) {
            int p = atomicAdd(&g_cur[c], 1);
            g_src[p] = s;
        }
    }
}

// ------------------------------------------------------------------
// one block: Wc = W1 @ W2 -> g_Wch (fp16, transposed [n][k]); bv = b1 @ W2
__global__ __launch_bounds__(256) void k_wc(
    const float* __restrict__ W1, const float* __restrict__ W2,
    const float* __restrict__ b1)
{
    __shared__ float w1s[64 * 64];
    __shared__ float w2s[64 * 64];
    int t = threadIdx.x;
    for (int i = t; i < 1024; i += 256) {
        ((float4*)w1s)[i] = ((const float4*)W1)[i];
        ((float4*)w2s)[i] = ((const float4*)W2)[i];
    }
    __syncthreads();
    int row = t >> 2;            // k index of Wc
    int cb  = (t & 3) * 16;      // n base
    float acc[16];
#pragma unroll
    for (int j = 0; j < 16; ++j) acc[j] = 0.f;
    for (int k = 0; k < 64; ++k) {
        float a = w1s[row * 64 + k];
#pragma unroll
        for (int j = 0; j < 16; ++j)
            acc[j] = fmaf(a, w2s[k * 64 + cb + j], acc[j]);
    }
#pragma unroll
    for (int j = 0; j < 16; ++j)
        g_Wch[(cb + j) * 64 + row] = __float2half(acc[j]);   // [n][k]
    if (t < 64) {
        float s = 0.f;
        for (int k = 0; k < 64; ++k) s = fmaf(b1[k], w2s[k * 64 + t], s);
        g_bv[t] = s;
    }
}

// ------------------------------------------------------------------
// HMMA GEMM: zs[r,:] = dinv[r] * (x[r,:] @ Wc)  -> fp16 g_zh
// 128 rows/block, 8 warps: each warp m16 x n64 via mma.m16n8k16, fp32 accum.
__global__ __launch_bounds__(256) void k_gemm(
    const float* __restrict__ xa, const float* __restrict__ xb)
{
    __shared__ __align__(16) __half As[128][72];   // A tile / output staging
    __shared__ __align__(16) __half Bs[64][72];    // Wc^T [n][k]
    int tid = threadIdx.x;
    int warp = tid >> 5, lane = tid & 31;
    int block_row = blockIdx.x * GEMM_ROWS;

    // stage B (4096 halves): 4 threads/row, 2 uint4 each
    {
        int r = tid >> 2, seg = tid & 3;
        const uint4* src = (const uint4*)(g_Wch + r * 64 + seg * 16);
        *(uint4*)(&Bs[r][seg * 16])     = src[0];
        *(uint4*)(&Bs[r][seg * 16 + 8]) = src[1];
    }
    // stage A: 128 rows x 64 fp32 -> fp16 (clamped tail rows; stores guarded)
#pragma unroll
    for (int p = 0; p < 8; ++p) {
        int r = p * 16 + (tid >> 4);
        int c = (tid & 15) * 4;
        int gr = block_row + r;
        int cr = (gr < N_NODES) ? gr : (N_NODES - 1);
        const float* xrow = (cr < N_USERS)
            ? (xa + (size_t)cr * DIM)
            : (xb + (size_t)(cr - N_USERS) * DIM);
        float4 v = *(const float4*)(xrow + c);
        *(__half2*)(&As[r][c])     = __floats2half2_rn(v.x, v.y);
        *(__half2*)(&As[r][c + 2]) = __floats2half2_rn(v.z, v.w);
    }
    __syncthreads();

    int g = lane >> 2, tig = lane & 3;
    float acc[8][4];
#pragma unroll
    for (int n = 0; n < 8; ++n)
#pragma unroll
        for (int j = 0; j < 4; ++j) acc[n][j] = 0.f;

#pragma unroll
    for (int kc = 0; kc < 4; ++kc) {
        unsigned a0 = *(unsigned*)(&As[warp * 16 + g][kc * 16 + tig * 2]);
        unsigned a1 = *(unsigned*)(&As[warp * 16 + g + 8][kc * 16 + tig * 2]);
        unsigned a2 = *(unsigned*)(&As[warp * 16 + g][kc * 16 + tig * 2 + 8]);
        unsigned a3 = *(unsigned*)(&As[warp * 16 + g + 8][kc * 16 + tig * 2 + 8]);
#pragma unroll
        for (int n = 0; n < 8; ++n) {
            unsigned b0 = *(unsigned*)(&Bs[n * 8 + g][kc * 16 + tig * 2]);
            unsigned b1 = *(unsigned*)(&Bs[n * 8 + g][kc * 16 + tig * 2 + 8]);
            asm volatile(
                "mma.sync.aligned.m16n8k16.row.col.f32.f16.f16.f32 "
                "{%0,%1,%2,%3}, {%4,%5,%6,%7}, {%8,%9}, {%0,%1,%2,%3};"
                : "+f"(acc[n][0]), "+f"(acc[n][1]), "+f"(acc[n][2]), "+f"(acc[n][3])
                : "r"(a0), "r"(a1), "r"(a2), "r"(a3), "r"(b0), "r"(b1));
        }
    }
    __syncthreads();   // done reading As; reuse as output staging

    int r0 = warp * 16 + g, r1 = r0 + 8;
    int gr0 = block_row + r0, gr1 = block_row + r1;
    float d0 = g_dinv[(gr0 < N_NODES) ? gr0 : (N_NODES - 1)];
    float d1 = g_dinv[(gr1 < N_NODES) ? gr1 : (N_NODES - 1)];
#pragma unroll
    for (int n = 0; n < 8; ++n) {
        *(__half2*)(&As[r0][n * 8 + tig * 2]) =
            __floats2half2_rn(acc[n][0] * d0, acc[n][1] * d0);
        *(__half2*)(&As[r1][n * 8 + tig * 2]) =
            __floats2half2_rn(acc[n][2] * d1, acc[n][3] * d1);
    }
    __syncthreads();
    // coalesced fp16 store: 128 rows x 8 uint4 segments
#pragma unroll
    for (int p = 0; p < 4; ++p) {
        int idx = p * 256 + tid;
        int r = idx >> 3, seg = idx & 7;
        int gr = block_row + r;
        if (gr < N_NODES)
            *(uint4*)(g_zh + (size_t)gr * DIM + seg * 8) = *(uint4*)(&As[r][seg * 8]);
    }
}

// ------------------------------------------------------------------
// hop 1: u1[c,:] = dinv^2[c] * (zs[c,:] + sum zs[src,:])   (g_zh -> g_hh)
//        lane0 accumulates sum dinv[src] -> a[c] = dinv[c]*(dinv[c]+sum)
__global__ __launch_bounds__(256) void k_agg1()
{
    int t = blockIdx.x * blockDim.x + threadIdx.x;
    int node = t >> 3;
    if (node >= N_NODES) return;
    int lane = (t & 7) * 8;
    bool lead = (t & 7) == 0;

    float acc[8] = {0.f, 0.f, 0.f, 0.f, 0.f, 0.f, 0.f, 0.f};
    float asum = 0.f;
    h8_add(acc, *(const uint4*)(g_zh + (size_t)node * DIM + lane));  // self
    int s0 = g_off[node];
    int cnt = g_cur[node] - s0;
    for (int i = 0; i < cnt; ++i) {
        int src = g_src[s0 + i];
        h8_add(acc, *(const uint4*)(g_zh + (size_t)src * DIM + lane));
        if (lead) asum += g_dinv[src];
    }
    float dn = g_dinv[node];
    float d2 = dn * dn;
    __half2 h0 = __floats2half2_rn(d2 * acc[0], d2 * acc[1]);
    __half2 h1 = __floats2half2_rn(d2 * acc[2], d2 * acc[3]);
    __half2 h2 = __floats2half2_rn(d2 * acc[4], d2 * acc[5]);
    __half2 h3 = __floats2half2_rn(d2 * acc[6], d2 * acc[7]);
    uint4 val;
    val.x = *(unsigned int*)&h0; val.y = *(unsigned int*)&h1;
    val.z = *(unsigned int*)&h2; val.w = *(unsigned int*)&h3;
    *(uint4*)(g_hh + (size_t)node * DIM + lane) = val;
    if (lead) g_a[node] = dn * (dn + asum);
}

// hop 2 + epilogue: out[c,:] = dinv[c]*(u1[c,:] + sum u1[src,:]) + a[c]*bv + b2
__global__ __launch_bounds__(256) void k_agg2(
    const float* __restrict__ b2, float* __restrict__ out)
{
    int t = blockIdx.x * blockDim.x + threadIdx.x;
    int node = t >> 3;
    if (node >= N_NODES) return;
    int lane = (t & 7) * 8;

    float acc[8] = {0.f, 0.f, 0.f, 0.f, 0.f, 0.f, 0.f, 0.f};
    h8_add(acc, *(const uint4*)(g_hh + (size_t)node * DIM + lane));  // self
    int s0 = g_off[node];
    int cnt = g_cur[node] - s0;
    for (int i = 0; i < cnt; ++i) {
        int src = g_src[s0 + i];
        h8_add(acc, *(const uint4*)(g_hh + (size_t)src * DIM + lane));
    }
    float dn = g_dinv[node];
    float av = g_a[node];
    float4 bv0 = *(const float4*)(g_bv + lane);
    float4 bv1 = *(const float4*)(g_bv + lane + 4);
    float4 b20 = *(const float4*)(b2 + lane);
    float4 b21 = *(const float4*)(b2 + lane + 4);
    float* dst = out + (size_t)node * DIM + lane;
    float4 o0 = make_float4(
        fmaf(dn, acc[0], fmaf(av, bv0.x, b20.x)),
        fmaf(dn, acc[1], fmaf(av, bv0.y, b20.y)),
        fmaf(dn, acc[2], fmaf(av, bv0.z, b20.z)),
        fmaf(dn, acc[3], fmaf(av, bv0.w, b20.w)));
    float4 o1 = make_float4(
        fmaf(dn, acc[4], fmaf(av, bv1.x, b21.x)),
        fmaf(dn, acc[5], fmaf(av, bv1.y, b21.y)),
        fmaf(dn, acc[6], fmaf(av, bv1.z, b21.z)),
        fmaf(dn, acc[7], fmaf(av, bv1.w, b21.w)));
    *(float4*)dst       = o0;
    *(float4*)(dst + 4) = o1;
}

// ------------------------------------------------------------------
extern "C" void kernel_launch(void* const* d_in, const int* in_sizes, int n_in,
                              void* d_out, int out_size)
{
    const void*  ei   = d_in[0];
    const float* user = (const float*)d_in[1];
    const float* item = (const float*)d_in[2];
    const float* W1   = (const float*)d_in[3];
    const float* b1   = (const float*)d_in[4];
    const float* W2   = (const float*)d_in[5];
    const float* b2   = (const float*)d_in[6];
    float* out        = (float*)d_out;
    int E = in_sizes[0] / 2;

    int zb  = (N_NODES + 255) / 256;
    int eb2 = (E / 2 + 255) / 256;
    int agg_blocks  = (N_NODES * 8 + 255) / 256;        // 6250
    int gemm_blocks = (N_NODES + GEMM_ROWS - 1) / GEMM_ROWS;  // 1563

    // one-time infra (created on the first, non-captured, correctness call)
    static cudaStream_t s_aux = nullptr;
    static cudaEvent_t ev_fork = nullptr, ev_wc = nullptr, ev_fill = nullptr,
                       ev_scan = nullptr;
    if (s_aux == nullptr) {
        cudaStreamCreateWithFlags(&s_aux, cudaStreamNonBlocking);
        cudaEventCreateWithFlags(&ev_fork, cudaEventDisableTiming);
        cudaEventCreateWithFlags(&ev_wc,   cudaEventDisableTiming);
        cudaEventCreateWithFlags(&ev_fill, cudaEventDisableTiming);
        cudaEventCreateWithFlags(&ev_scan, cudaEventDisableTiming);
    }

    // fork: aux stream computes Wc (independent of graph prep)
    cudaEventRecord(ev_fork, 0);
    cudaStreamWaitEvent(s_aux, ev_fork, 0);
    k_wc<<<1, 256, 0, s_aux>>>(W1, W2, b1);
    cudaEventRecord(ev_wc, s_aux);

    // main stream: graph prep chain (g_cnt arrives zeroed — self-cleaning)
    k_hist<<<eb2, 256>>>(ei, E);
    k_scan1<<<NUM_SCAN_BLOCKS, 256>>>();
    k_scan3<<<zb, 256>>>();

    // fork: fill (L2/atomic-bound) concurrent with gemm (tensor/mem-bound)
    cudaEventRecord(ev_scan, 0);
    cudaStreamWaitEvent(s_aux, ev_scan, 0);
    k_fill<<<eb2, 256, 0, s_aux>>>(ei, E);
    cudaEventRecord(ev_fill, s_aux);

    cudaStreamWaitEvent(0, ev_wc, 0);          // gemm needs Wch + dinv
    k_gemm<<<gemm_blocks, 256>>>(user, item);  // zs (fp16) -> g_zh

    // join: aggregation needs both gemm (main) and fill (aux)
    cudaStreamWaitEvent(0, ev_fill, 0);
    k_agg1<<<agg_blocks, 256>>>();             // u1 (fp16), a
    k_agg2<<<agg_blocks, 256>>>(b2, out);      // out = A u1 + a*bv + b2
}